// round 13
// baseline (speedup 1.0000x reference)
#include <cuda_runtime.h>
#include <cuda_bf16.h>
#include <cuda_fp16.h>
#include <math.h>
#include <stdint.h>

#define NN 50000
#define EE 300000
#define DD 256
#define FF 1024
#define CC 40
#define AB_PITCH 80

// ---------------- scratch (static device globals; no allocation) ----------------
__device__ __half g_X16[NN * DD];       // inter-layer activations, fp16
__device__ float g_ns[NN];
__device__ float g_nd[NN];
__device__ int   g_degout[NN];
__device__ int   g_degin[NN];
__device__ int   g_fill[NN];
__device__ int   g_incl[49 * 1024];
__device__ int   g_bsum[64];
__device__ int   g_boff[64];
__device__ int   g_rowptr[NN + 1];
__device__ int   g_col[EE];
__device__ float g_bns[DD];
__device__ float g_bnq[DD];

// packed split-bf16 A planes written by spmm: per (rowblk, ktile): 128 rows x 80B
__device__ __align__(16) unsigned char g_Ah[391 * 8 * 10240];
__device__ __align__(16) unsigned char g_Al[391 * 8 * 10240];

// prepacked weights: per ktile: 256 n-rows x 80B = 20480 B (bf16 hi/lo planes)
__device__ __align__(16) unsigned char g_Wfc_h[32 * 20480];
__device__ __align__(16) unsigned char g_Wfc_l[32 * 20480];
__device__ __align__(16) unsigned char g_W1_h[8 * 20480];
__device__ __align__(16) unsigned char g_W1_l[8 * 20480];
__device__ __align__(16) unsigned char g_W2_h[8 * 20480];
__device__ __align__(16) unsigned char g_W2_l[8 * 20480];
__device__ __align__(16) unsigned char g_W3_h[8 * 20480];
__device__ __align__(16) unsigned char g_W3_l[8 * 20480];

// ================= helpers =================
__device__ __forceinline__ uint32_t smem_to_u32(const void* p) {
    uint32_t a;
    asm("{ .reg .u64 t; cvta.to.shared.u64 t, %1; cvt.u32.u64 %0, t; }" : "=r"(a) : "l"(p));
    return a;
}
__device__ __forceinline__ void ldm4(uint32_t* r, uint32_t addr) {
    asm volatile("ldmatrix.sync.aligned.m8n8.x4.shared.b16 {%0,%1,%2,%3}, [%4];"
        : "=r"(r[0]), "=r"(r[1]), "=r"(r[2]), "=r"(r[3]) : "r"(addr));
}
__device__ __forceinline__ void mma_bf16(float* d, const uint32_t* a, const uint32_t* b) {
    asm volatile(
        "mma.sync.aligned.m16n8k16.row.col.f32.bf16.bf16.f32 "
        "{%0,%1,%2,%3}, {%4,%5,%6,%7}, {%8,%9}, {%0,%1,%2,%3};"
        : "+f"(d[0]), "+f"(d[1]), "+f"(d[2]), "+f"(d[3])
        : "r"(a[0]), "r"(a[1]), "r"(a[2]), "r"(a[3]), "r"(b[0]), "r"(b[1]));
}
__device__ __forceinline__ void cp16(uint32_t saddr, const void* gaddr) {
    asm volatile("cp.async.cg.shared.global [%0], [%1], 16;" :: "r"(saddr), "l"(gaddr));
}
#define CP_COMMIT() asm volatile("cp.async.commit_group;" ::: "memory")
#define CP_WAIT0()  asm volatile("cp.async.wait_group 0;" ::: "memory")

__device__ __forceinline__ void split2(float x0, float x1, uint32_t& ph, uint32_t& pl) {
    __nv_bfloat16 h0 = __float2bfloat16(x0), h1 = __float2bfloat16(x1);
    float r0 = x0 - __bfloat162float(h0), r1 = x1 - __bfloat162float(h1);
    __nv_bfloat16 l0 = __float2bfloat16(r0), l1 = __float2bfloat16(r1);
    ph = ((uint32_t)__bfloat16_as_ushort(h1) << 16) | (uint32_t)__bfloat16_as_ushort(h0);
    pl = ((uint32_t)__bfloat16_as_ushort(l1) << 16) | (uint32_t)__bfloat16_as_ushort(l0);
}

// FMA-pipe exp for x <= 0 (magic-number exp2 + degree-5 poly)
__device__ __forceinline__ float fexp_neg(float x) {
    float z = fmaxf(x * 1.44269504f, -126.0f);
    float t = z + 12582912.0f;
    float n = t - 12582912.0f;
    float f = z - n;
    int   i = __float_as_int(t);
    float p = 1.3333558146e-3f;
    p = fmaf(p, f, 9.6181291076e-3f);
    p = fmaf(p, f, 5.5504108664e-2f);
    p = fmaf(p, f, 2.4022650696e-1f);
    p = fmaf(p, f, 6.9314718056e-1f);
    p = fmaf(p, f, 1.0f);
    float s = __int_as_float((((i & 0x7FFFFF) - 0x400000 + 127) << 23));
    return p * s;
}

// interleaved 12-MMA block: same per-acc product order (Bh, Bl, then Al·Bh),
// but same-acc revisit distance 4 instead of 1 (breaks HMMA RAW chains)
#define MMA_BLOCK(accp, ah, al, rh, rl, np)                     \
    do {                                                        \
        mma_bf16(accp[0][(np)*2 + 0], ah[0], rh + 0);           \
        mma_bf16(accp[1][(np)*2 + 0], ah[1], rh + 0);           \
        mma_bf16(accp[0][(np)*2 + 1], ah[0], rh + 2);           \
        mma_bf16(accp[1][(np)*2 + 1], ah[1], rh + 2);           \
        mma_bf16(accp[0][(np)*2 + 0], ah[0], rl + 0);           \
        mma_bf16(accp[1][(np)*2 + 0], ah[1], rl + 0);           \
        mma_bf16(accp[0][(np)*2 + 1], ah[0], rl + 2);           \
        mma_bf16(accp[1][(np)*2 + 1], ah[1], rl + 2);           \
        mma_bf16(accp[0][(np)*2 + 0], al[0], rh + 0);           \
        mma_bf16(accp[1][(np)*2 + 0], al[1], rh + 0);           \
        mma_bf16(accp[0][(np)*2 + 1], al[0], rh + 2);           \
        mma_bf16(accp[1][(np)*2 + 1], al[1], rh + 2);           \
    } while (0)

// ---------------- graph prep ----------------
__global__ void k_zero_prep() {
    int i = blockIdx.x * 256 + threadIdx.x;
    if (i < NN) { g_degout[i] = 0; g_degin[i] = 0; g_fill[i] = 0; }
}
__global__ void k_count(const int* __restrict__ src, const int* __restrict__ dst) {
    int e = blockIdx.x * 256 + threadIdx.x;
    if (e < EE) { atomicAdd(&g_degout[src[e]], 1); atomicAdd(&g_degin[dst[e]], 1); }
}
__global__ void k_norms() {
    int i = blockIdx.x * 256 + threadIdx.x;
    if (i < NN) {
        g_ns[i] = rsqrtf((float)max(g_degout[i], 1));
        g_nd[i] = rsqrtf((float)max(g_degin[i], 1));
    }
}
__global__ void k_scan1() {
    __shared__ int s[1024];
    int tid = threadIdx.x;
    int i = blockIdx.x * 1024 + tid;
    int v = (i < NN) ? g_degin[i] : 0;
    s[tid] = v;
    __syncthreads();
    for (int off = 1; off < 1024; off <<= 1) {
        int t = (tid >= off) ? s[tid - off] : 0;
        __syncthreads(); s[tid] += t; __syncthreads();
    }
    g_incl[i] = s[tid];
    if (tid == 1023) g_bsum[blockIdx.x] = s[1023];
}
__global__ void k_scan2() {
    __shared__ int s[64];
    int tid = threadIdx.x;
    int v = (tid < 49) ? g_bsum[tid] : 0;
    s[tid] = v;
    __syncthreads();
    for (int off = 1; off < 64; off <<= 1) {
        int t = (tid >= off) ? s[tid - off] : 0;
        __syncthreads(); s[tid] += t; __syncthreads();
    }
    g_boff[tid] = s[tid] - v;
}
__global__ void k_scan3() {
    int i = blockIdx.x * 256 + threadIdx.x;
    if (i < NN) g_rowptr[i + 1] = g_incl[i] + g_boff[i >> 10];
    if (i == 0) g_rowptr[0] = 0;
}
__global__ void k_fill(const int* __restrict__ src, const int* __restrict__ dst) {
    int e = blockIdx.x * 256 + threadIdx.x;
    if (e < EE) {
        int d = dst[e];
        int pos = g_rowptr[d] + atomicAdd(&g_fill[d], 1);
        g_col[pos] = src[e];
    }
}

// ---------------- SpMM gather (fp16 X) -> packed split-bf16 planes (norm_d fused) ----------------
__global__ void k_spmm(const __half* __restrict__ X) {
    int node = blockIdx.x * 8 + threadIdx.y;
    if (node >= NN) return;
    int lane = threadIdx.x;
    float acc[8];
    #pragma unroll
    for (int i = 0; i < 8; i++) acc[i] = 0.f;

    int beg = g_rowptr[node], end = g_rowptr[node + 1];
    int e = beg;
    for (; e + 1 < end; e += 2) {
        int s0 = g_col[e], s1 = g_col[e + 1];
        float w0 = g_ns[s0], w1 = g_ns[s1];
        uint4 u0 = *(const uint4*)(X + (size_t)s0 * DD + lane * 8);
        uint4 u1 = *(const uint4*)(X + (size_t)s1 * DD + lane * 8);
        const __half2* h0 = (const __half2*)&u0;
        const __half2* h1 = (const __half2*)&u1;
        #pragma unroll
        for (int q = 0; q < 4; q++) {
            float2 f0 = __half22float2(h0[q]);
            float2 f1 = __half22float2(h1[q]);
            acc[q * 2 + 0] += w0 * f0.x + w1 * f1.x;
            acc[q * 2 + 1] += w0 * f0.y + w1 * f1.y;
        }
    }
    if (e < end) {
        int s0 = g_col[e];
        float w0 = g_ns[s0];
        uint4 u0 = *(const uint4*)(X + (size_t)s0 * DD + lane * 8);
        const __half2* h0 = (const __half2*)&u0;
        #pragma unroll
        for (int q = 0; q < 4; q++) {
            float2 f0 = __half22float2(h0[q]);
            acc[q * 2 + 0] += w0 * f0.x;
            acc[q * 2 + 1] += w0 * f0.y;
        }
    }
    float nd = g_nd[node];
    #pragma unroll
    for (int i = 0; i < 8; i++) acc[i] *= nd;

    uint4 vh, vl;
    split2(acc[0], acc[1], vh.x, vl.x);
    split2(acc[2], acc[3], vh.y, vl.y);
    split2(acc[4], acc[5], vh.z, vl.z);
    split2(acc[6], acc[7], vh.w, vl.w);
    size_t base = ((size_t)(node >> 7) * 8 + (lane >> 2)) * 10240
                + (uint32_t)((node & 127) * AB_PITCH + (lane & 3) * 16);
    *(uint4*)(g_Ah + base) = vh;
    *(uint4*)(g_Al + base) = vl;
}

// ---------------- weight prepack (bf16 split) ----------------
__global__ void k_prepack(const float* __restrict__ W, unsigned char* __restrict__ ph,
                          unsigned char* __restrict__ pl, int K) {
    int task = blockIdx.x * 256 + threadIdx.x;
    int nk8 = K >> 3;
    if (task >= DD * nk8) return;
    int n = task / nk8, k8 = task % nk8;
    int k0 = k8 << 3;
    float x[8];
    #pragma unroll
    for (int i = 0; i < 8; i++) x[i] = W[(size_t)(k0 + i) * DD + n];
    uint4 vh, vl;
    split2(x[0], x[1], vh.x, vl.x);
    split2(x[2], x[3], vh.y, vl.y);
    split2(x[4], x[5], vh.z, vl.z);
    split2(x[6], x[7], vh.w, vl.w);
    size_t off = (size_t)(k0 >> 5) * 20480 + (size_t)n * AB_PITCH + (k0 & 31) * 2;
    *(uint4*)(ph + off) = vh;
    *(uint4*)(pl + off) = vl;
}

// ================= 64x256 HMMA GEMM cores (bf16 3-product, 2 CTAs/SM) =================
#define SM_AL_OFF 5120
#define SM_BH_OFF 10240
#define SM_BL_OFF 30720
#define BUF_SZ 51200
#define SMEM_GEMM 102400

// ---- fc: fp32 A split on the fly; writes fp16 X ----
__global__ void __launch_bounds__(256, 2) hmma_gemm_fc(
    const float* __restrict__ A,
    const unsigned char* __restrict__ Bh_g, const unsigned char* __restrict__ Bl_g,
    const float* __restrict__ bias, __half* __restrict__ C, int M, int K)
{
    extern __shared__ __align__(16) unsigned char smem[];
    uint32_t sb = smem_to_u32(smem);
    int tid = threadIdx.x;
    int wid = tid >> 5, lane = tid & 31;
    int bm0 = blockIdx.x * 64;
    int nIter = K >> 5;

    int arow = tid >> 2;
    int akq = (tid & 3) * 8;
    int agr = bm0 + arow;
    bool avalid = (agr < M);
    const float* aptr = A + (size_t)(avalid ? agr : 0) * K + akq;
    uint32_t a_soff = (uint32_t)(arow * AB_PITCH + akq * 2);

    int wr = wid >> 2, wc = wid & 3;
    int mbase_w = wr * 32;
    int nbase_w = wc * 64;

    int lj = lane >> 3, lr = lane & 7;
    uint32_t aoffA = (uint32_t)(((lj & 1) * 8 + lr) * AB_PITCH + (lj >> 1) * 16);
    uint32_t aoffB = (uint32_t)(((lj >> 1) * 8 + lr) * AB_PITCH + (lj & 1) * 16);

    float acc[2][8][4];
    #pragma unroll
    for (int mt = 0; mt < 2; mt++)
        #pragma unroll
        for (int nt = 0; nt < 8; nt++)
            #pragma unroll
            for (int i = 0; i < 4; i++) acc[mt][nt][i] = 0.f;

    {
        for (int c = tid; c < 1280; c += 256) {
            cp16(sb + SM_BH_OFF + c * 16, Bh_g + c * 16);
            cp16(sb + SM_BL_OFF + c * 16, Bl_g + c * 16);
        }
        CP_COMMIT();
        float4 v0 = make_float4(0.f, 0.f, 0.f, 0.f), v1 = v0;
        if (avalid) { v0 = *(const float4*)(aptr); v1 = *(const float4*)(aptr + 4); }
        uint4 vh, vl;
        split2(v0.x, v0.y, vh.x, vl.x);
        split2(v0.z, v0.w, vh.y, vl.y);
        split2(v1.x, v1.y, vh.z, vl.z);
        split2(v1.z, v1.w, vh.w, vl.w);
        *(uint4*)(smem + a_soff) = vh;
        *(uint4*)(smem + SM_AL_OFF + a_soff) = vl;
        CP_WAIT0();
        __syncthreads();
    }

    for (int it = 0; it < nIter; it++) {
        uint32_t bufo = (uint32_t)((it & 1) * BUF_SZ);
        uint32_t nbufo = (uint32_t)(((it + 1) & 1) * BUF_SZ);
        bool more = (it + 1 < nIter);

        float4 v0 = make_float4(0.f, 0.f, 0.f, 0.f), v1 = v0;
        if (more) {
            size_t tb = (size_t)(it + 1) * 20480;
            for (int c = tid; c < 1280; c += 256) {
                cp16(sb + nbufo + SM_BH_OFF + c * 16, Bh_g + tb + c * 16);
                cp16(sb + nbufo + SM_BL_OFF + c * 16, Bl_g + tb + c * 16);
            }
            CP_COMMIT();
            if (avalid) {
                int k0 = (it + 1) << 5;
                v0 = *(const float4*)(aptr + k0);
                v1 = *(const float4*)(aptr + k0 + 4);
            }
        }

        #pragma unroll
        for (int ks = 0; ks < 2; ks++) {
            uint32_t kof = (uint32_t)(ks * 32);
            uint32_t ah[2][4], al[2][4];
            #pragma unroll
            for (int mt = 0; mt < 2; mt++) {
                uint32_t base = sb + bufo + (uint32_t)((mbase_w + mt * 16) * AB_PITCH) + kof + aoffA;
                ldm4(ah[mt], base);
                ldm4(al[mt], base + SM_AL_OFF);
            }
            #pragma unroll
            for (int np = 0; np < 4; np++) {
                uint32_t bbase = sb + bufo + SM_BH_OFF + (uint32_t)((nbase_w + np * 16) * AB_PITCH) + kof + aoffB;
                uint32_t rh[4], rl[4];
                ldm4(rh, bbase);
                ldm4(rl, bbase + 20480);
                MMA_BLOCK(acc, ah, al, rh, rl, np);
            }
        }

        if (more) {
            uint4 vh, vl;
            split2(v0.x, v0.y, vh.x, vl.x);
            split2(v0.z, v0.w, vh.y, vl.y);
            split2(v1.x, v1.y, vh.z, vl.z);
            split2(v1.z, v1.w, vh.w, vl.w);
            *(uint4*)(smem + nbufo + a_soff) = vh;
            *(uint4*)(smem + nbufo + SM_AL_OFF + a_soff) = vl;
            CP_WAIT0();
        }
        __syncthreads();
    }

    int g = lane >> 2, t2 = (lane & 3) * 2;
    #pragma unroll
    for (int mt = 0; mt < 2; mt++) {
        int r0 = bm0 + mbase_w + mt * 16 + g;
        int r1 = r0 + 8;
        #pragma unroll
        for (int nt = 0; nt < 8; nt++) {
            int c = nbase_w + nt * 8 + t2;
            float b0 = __ldg(&bias[c]), b1 = __ldg(&bias[c + 1]);
            if (r0 < M) *(__half2*)(C + (size_t)r0 * DD + c) =
                __floats2half2_rn(acc[mt][nt][0] + b0, acc[mt][nt][1] + b1);
            if (r1 < M) *(__half2*)(C + (size_t)r1 * DD + c) =
                __floats2half2_rn(acc[mt][nt][2] + b0, acc[mt][nt][3] + b1);
        }
    }
}

// ---- layer GEMM: packed split-bf16 A; output fp16 (layers 1,2) or fp32 (layer 3) ----
template <bool HALF_OUT>
__global__ void __launch_bounds__(256, 2) hmma_gemm_pk(
    const unsigned char* __restrict__ Ah_g, const unsigned char* __restrict__ Al_g,
    const unsigned char* __restrict__ Bh_g, const unsigned char* __restrict__ Bl_g,
    const float* __restrict__ bias, void* __restrict__ Cv, int M)
{
    extern __shared__ __align__(16) unsigned char smem[];
    uint32_t sb = smem_to_u32(smem);
    int tid = threadIdx.x;
    int wid = tid >> 5, lane = tid & 31;
    int bm0 = blockIdx.x * 64;
    const int nIter = 8;
    size_t abase = (size_t)(blockIdx.x >> 1) * 8 * 10240 + (size_t)(blockIdx.x & 1) * 5120;

    int wr = wid >> 2, wc = wid & 3;
    int mbase_w = wr * 32;
    int nbase_w = wc * 64;

    int lj = lane >> 3, lr = lane & 7;
    uint32_t aoffA = (uint32_t)(((lj & 1) * 8 + lr) * AB_PITCH + (lj >> 1) * 16);
    uint32_t aoffB = (uint32_t)(((lj >> 1) * 8 + lr) * AB_PITCH + (lj & 1) * 16);

    float acc[2][8][4];
    #pragma unroll
    for (int mt = 0; mt < 2; mt++)
        #pragma unroll
        for (int nt = 0; nt < 8; nt++)
            #pragma unroll
            for (int i = 0; i < 4; i++) acc[mt][nt][i] = 0.f;

    {
        for (int c = tid; c < 320; c += 256) {
            cp16(sb + c * 16, Ah_g + abase + c * 16);
            cp16(sb + SM_AL_OFF + c * 16, Al_g + abase + c * 16);
        }
        for (int c = tid; c < 1280; c += 256) {
            cp16(sb + SM_BH_OFF + c * 16, Bh_g + c * 16);
            cp16(sb + SM_BL_OFF + c * 16, Bl_g + c * 16);
        }
        CP_COMMIT();
        CP_WAIT0();
        __syncthreads();
    }

    for (int it = 0; it < nIter; it++) {
        uint32_t bufo = (uint32_t)((it & 1) * BUF_SZ);
        uint32_t nbufo = (uint32_t)(((it + 1) & 1) * BUF_SZ);
        bool more = (it + 1 < nIter);

        if (more) {
            size_t ta = abase + (size_t)(it + 1) * 10240;
            size_t tb = (size_t)(it + 1) * 20480;
            for (int c = tid; c < 320; c += 256) {
                cp16(sb + nbufo + c * 16, Ah_g + ta + c * 16);
                cp16(sb + nbufo + SM_AL_OFF + c * 16, Al_g + ta + c * 16);
            }
            for (int c = tid; c < 1280; c += 256) {
                cp16(sb + nbufo + SM_BH_OFF + c * 16, Bh_g + tb + c * 16);
                cp16(sb + nbufo + SM_BL_OFF + c * 16, Bl_g + tb + c * 16);
            }
            CP_COMMIT();
        }

        #pragma unroll
        for (int ks = 0; ks < 2; ks++) {
            uint32_t kof = (uint32_t)(ks * 32);
            uint32_t ah[2][4], al[2][4];
            #pragma unroll
            for (int mt = 0; mt < 2; mt++) {
                uint32_t base = sb + bufo + (uint32_t)((mbase_w + mt * 16) * AB_PITCH) + kof + aoffA;
                ldm4(ah[mt], base);
                ldm4(al[mt], base + SM_AL_OFF);
            }
            #pragma unroll
            for (int np = 0; np < 4; np++) {
                uint32_t bbase = sb + bufo + SM_BH_OFF + (uint32_t)((nbase_w + np * 16) * AB_PITCH) + kof + aoffB;
                uint32_t rh[4], rl[4];
                ldm4(rh, bbase);
                ldm4(rl, bbase + 20480);
                MMA_BLOCK(acc, ah, al, rh, rl, np);
            }
        }

        if (more) CP_WAIT0();
        __syncthreads();
    }

    int g = lane >> 2, t2 = (lane & 3) * 2;
    #pragma unroll
    for (int mt = 0; mt < 2; mt++) {
        int r0 = bm0 + mbase_w + mt * 16 + g;
        int r1 = r0 + 8;
        #pragma unroll
        for (int nt = 0; nt < 8; nt++) {
            int c = nbase_w + nt * 8 + t2;
            float b0 = __ldg(&bias[c]), b1 = __ldg(&bias[c + 1]);
            if (HALF_OUT) {
                __half* C = (__half*)Cv;
                if (r0 < M) *(__half2*)(C + (size_t)r0 * DD + c) =
                    __floats2half2_rn(acc[mt][nt][0] + b0, acc[mt][nt][1] + b1);
                if (r1 < M) *(__half2*)(C + (size_t)r1 * DD + c) =
                    __floats2half2_rn(acc[mt][nt][2] + b0, acc[mt][nt][3] + b1);
            } else {
                float* C = (float*)Cv;
                if (r0 < M) *(float2*)(C + (size_t)r0 * DD + c) =
                    make_float2(acc[mt][nt][0] + b0, acc[mt][nt][1] + b1);
                if (r1 < M) *(float2*)(C + (size_t)r1 * DD + c) =
                    make_float2(acc[mt][nt][2] + b0, acc[mt][nt][3] + b1);
            }
        }
    }
}

// ---------------- BatchNorm + ELU (fp16 X) ----------------
__global__ void k_zero_bn() {
    int c = threadIdx.x;
    g_bns[c] = 0.f;
    g_bnq[c] = 0.f;
}
__global__ void k_bn_stats(const __half* __restrict__ X) {
    int c = threadIdx.x;
    int r0 = blockIdx.x * 256;
    int r1 = min(r0 + 256, NN);
    float s = 0.f, q = 0.f;
    for (int r = r0; r < r1; r++) {
        float v = __half2float(X[(size_t)r * DD + c]);
        s += v; q += v * v;
    }
    atomicAdd(&g_bns[c], s);
    atomicAdd(&g_bnq[c], q);
}
__global__ void k_bn_apply(__half* __restrict__ X,
                           const float* __restrict__ gamma,
                           const float* __restrict__ beta) {
    int idx = blockIdx.x * 256 + threadIdx.x;
    if (idx >= NN * (DD / 2)) return;
    int c2 = idx & 127;
    int c = c2 * 2;
    const float invN = 1.f / (float)NN;
    float2 sm = *(const float2*)&g_bns[c];
    float2 sq = *(const float2*)&g_bnq[c];
    float2 gm = *(const float2*)&gamma[c];
    float2 bt = *(const float2*)&beta[c];
    __half2 hx = ((__half2*)X)[idx];
    float2 x = __half22float2(hx);
    float mu, var, sc;
    float2 y;
    mu = sm.x * invN; var = sq.x * invN - mu * mu; sc = gm.x * rsqrtf(var + 1e-5f);
    y.x = sc * (x.x - mu) + bt.x;
    mu = sm.y * invN; var = sq.y * invN - mu * mu; sc = gm.y * rsqrtf(var + 1e-5f);
    y.y = sc * (x.y - mu) + bt.y;
    y.x = (y.x > 0.f) ? y.x : (__expf(y.x) - 1.f);
    y.y = (y.y > 0.f) ? y.y : (fexp_neg(y.y) - 1.f);
    ((__half2*)X)[idx] = __floats2half2_rn(y.x, y.y);
}

// ---------------- logits GEMM (reads fp32 out) ----------------
__global__ __launch_bounds__(320) void k_logits(
    const float* __restrict__ X, const float* __restrict__ W,
    const float* __restrict__ bias, float* __restrict__ O, int M)
{
    __shared__ float Xs[32][68];
    __shared__ float Ws[32][40];
    int tid = threadIdx.x;
    int bm0 = blockIdx.x * 64;
    int rg = tid / 40;
    int col = tid % 40;
    float acc[8];
    #pragma unroll
    for (int i = 0; i < 8; i++) acc[i] = 0.f;

    for (int k0 = 0; k0 < DD; k0 += 32) {
        for (int idx = tid; idx < 512; idx += 320) {
            int row = idx >> 3;
            int kq = idx & 7;
            float4 v = make_float4(0.f, 0.f, 0.f, 0.f);
            int gr = bm0 + row;
            if (gr < M) v = *(const float4*)(X + (size_t)gr * DD + k0 + kq * 4);
            Xs[kq * 4 + 0][row] = v.x;
            Xs[kq * 4 + 1][row] = v.y;
            Xs[kq * 4 + 2][row] = v.z;
            Xs[kq * 4 + 3][row] = v.w;
        }
        for (int idx = tid; idx < 1280; idx += 320) {
            int k = idx / 40, c = idx % 40;
            Ws[k][c] = W[(size_t)(k0 + k) * CC + c];
        }
        __syncthreads();
        #pragma unroll
        for (int kk = 0; kk < 32; kk++) {
            float w = Ws[kk][col];
            float a0[4], a1[4];
            *(float4*)&a0[0] = *(float4*)&Xs[kk][rg * 8];
            *(float4*)&a1[0] = *(float4*)&Xs[kk][rg * 8 + 4];
            acc[0] += a0[0] * w; acc[1] += a0[1] * w;
            acc[2] += a0[2] * w; acc[3] += a0[3] * w;
            acc[4] += a1[0] * w; acc[5] += a1[1] * w;
            acc[6] += a1[2] * w; acc[7] += a1[3] * w;
        }
        __syncthreads();
    }
    float b = bias[col];
    #pragma unroll
    for (int i = 0; i < 8; i++) {
        int r = bm0 + rg * 8 + i;
        if (r < M) O[(size_t)r * CC + col] = acc[i] + b;
    }
}

// ---------------- static stream/event init ----------------
struct SideRes {
    cudaStream_t sB;
    cudaEvent_t evFork, evJoin;
    SideRes() {
        cudaStreamCreateWithFlags(&sB, cudaStreamNonBlocking);
        cudaEventCreateWithFlags(&evFork, cudaEventDisableTiming);
        cudaEventCreateWithFlags(&evJoin, cudaEventDisableTiming);
        cudaFuncSetAttribute(hmma_gemm_fc, cudaFuncAttributeMaxDynamicSharedMemorySize, SMEM_GEMM);
        cudaFuncSetAttribute(hmma_gemm_pk<true>,  cudaFuncAttributeMaxDynamicSharedMemorySize, SMEM_GEMM);
        cudaFuncSetAttribute(hmma_gemm_pk<false>, cudaFuncAttributeMaxDynamicSharedMemorySize, SMEM_GEMM);
    }
};
static SideRes g_sr;

// ---------------- driver ----------------
extern "C" void kernel_launch(void* const* d_in, const int* in_sizes, int n_in,
                              void* d_out, int out_size)
{
    const float* feat  = (const float*)d_in[0];
    const int*   src   = (const int*)d_in[1];
    const int*   dst   = (const int*)d_in[2];
    const float* W_fc  = (const float*)d_in[3];
    const float* b_fc  = (const float*)d_in[4];
    const float* W1    = (const float*)d_in[5];
    const float* b1    = (const float*)d_in[6];
    const float* W2    = (const float*)d_in[7];
    const float* b2    = (const float*)d_in[8];
    const float* W3    = (const float*)d_in[9];
    const float* b3    = (const float*)d_in[10];
    const float* gamma = (const float*)d_in[11];
    const float* beta  = (const float*)d_in[12];
    const float* W_lin = (const float*)d_in[13];
    const float* b_lin = (const float*)d_in[14];
    float* out = (float*)d_out;

    __half* gX16; cudaGetSymbolAddress((void**)&gX16, g_X16);
    unsigned char *gAh, *gAl;
    cudaGetSymbolAddress((void**)&gAh, g_Ah);
    cudaGetSymbolAddress((void**)&gAl, g_Al);
    unsigned char *pFh, *pFl, *p1h, *p1l, *p2h, *p2l, *p3h, *p3l;
    cudaGetSymbolAddress((void**)&pFh, g_Wfc_h);
    cudaGetSymbolAddress((void**)&pFl, g_Wfc_l);
    cudaGetSymbolAddress((void**)&p1h, g_W1_h);
    cudaGetSymbolAddress((void**)&p1l, g_W1_l);
    cudaGetSymbolAddress((void**)&p2h, g_W2_h);
    cudaGetSymbolAddress((void**)&p2l, g_W2_l);
    cudaGetSymbolAddress((void**)&p3h, g_W3_h);
    cudaGetSymbolAddress((void**)&p3l, g_W3_l);

    const int NB_N = (NN + 255) / 256;
    const int NB_E = (EE + 255) / 256;
    const int GEMM_GRID = (NN + 63) / 64;   // 782
    dim3 spmm_block(32, 8);
    int spmm_grid = (NN + 7) / 8;
    int bn_grid = (NN * (DD / 2) + 255) / 256;

    // fork
    cudaEventRecord(g_sr.evFork, 0);
    cudaStreamWaitEvent(g_sr.sB, g_sr.evFork, 0);

    k_zero_prep<<<NB_N, 256, 0, g_sr.sB>>>();
    k_count<<<NB_E, 256, 0, g_sr.sB>>>(src, dst);
    k_prepack<<<(DD * (FF / 8) + 255) / 256, 256>>>(W_fc, pFh, pFl, FF);              // main
    hmma_gemm_fc<<<GEMM_GRID, 256, SMEM_GEMM>>>(feat, pFh, pFl, b_fc, gX16, NN, FF);  // main
    k_norms<<<NB_N, 256, 0, g_sr.sB>>>();
    k_scan1<<<49, 1024, 0, g_sr.sB>>>();
    k_scan2<<<1, 64, 0, g_sr.sB>>>();
    k_scan3<<<NB_N, 256, 0, g_sr.sB>>>();
    k_fill<<<NB_E, 256, 0, g_sr.sB>>>(src, dst);
    k_prepack<<<(DD * (DD / 8) + 255) / 256, 256, 0, g_sr.sB>>>(W1, p1h, p1l, DD);
    k_prepack<<<(DD * (DD / 8) + 255) / 256, 256, 0, g_sr.sB>>>(W2, p2h, p2l, DD);
    k_prepack<<<(DD * (DD / 8) + 255) / 256, 256, 0, g_sr.sB>>>(W3, p3h, p3l, DD);
    k_zero_bn<<<1, 256, 0, g_sr.sB>>>();
    cudaEventRecord(g_sr.evJoin, g_sr.sB);

    // join
    cudaStreamWaitEvent(0, g_sr.evJoin, 0);

    // layer 1
    k_spmm<<<spmm_grid, spmm_block>>>(gX16);
    hmma_gemm_pk<true><<<GEMM_GRID, 256, SMEM_GEMM>>>(gAh, gAl, p1h, p1l, b1, gX16, NN);
    k_bn_stats<<<NB_N, 256>>>(gX16);
    k_bn_apply<<<bn_grid, 256>>>(gX16, gamma, beta);
    k_zero_bn<<<1, 256>>>();

    // layer 2
    k_spmm<<<spmm_grid, spmm_block>>>(gX16);
    hmma_gemm_pk<true><<<GEMM_GRID, 256, SMEM_GEMM>>>(gAh, gAl, p2h, p2l, b2, gX16, NN);
    k_bn_stats<<<NB_N, 256>>>(gX16);
    k_bn_apply<<<bn_grid, 256>>>(gX16, gamma, beta);

    // layer 3 -> fp32 features into d_out[0 : N*D)
    k_spmm<<<spmm_grid, spmm_block>>>(gX16);
    hmma_gemm_pk<false><<<GEMM_GRID, 256, SMEM_GEMM>>>(gAh, gAl, p3h, p3l, b3, out, NN);

    // logits -> d_out[N*D : )
    k_logits<<<(NN + 63) / 64, 320>>>(out, W_lin, b_lin, out + (size_t)NN * DD, NN);
}

// round 14
// speedup vs baseline: 1.0204x; 1.0204x over previous
#include <cuda_runtime.h>
#include <cuda_bf16.h>
#include <cuda_fp16.h>
#include <math.h>
#include <stdint.h>

#define NN 50000
#define EE 300000
#define DD 256
#define FF 1024
#define CC 40
#define AB_PITCH 80

// ---------------- scratch (static device globals; no allocation) ----------------
__device__ __half g_X16[NN * DD];       // inter-layer activations, fp16
__device__ float g_ns[NN];
__device__ float g_nd[NN];
__device__ int   g_degout[NN];
__device__ int   g_degin[NN];
__device__ int   g_fill[NN];
__device__ int   g_incl[49 * 1024];
__device__ int   g_bsum[64];
__device__ int   g_boff[64];
__device__ int   g_rowptr[NN + 1];
__device__ int   g_col[EE];
__device__ float g_bns[DD];
__device__ float g_bnq[DD];

// packed split-bf16 A planes written by spmm: per (rowblk, ktile): 128 rows x 80B
__device__ __align__(16) unsigned char g_Ah[391 * 8 * 10240];
__device__ __align__(16) unsigned char g_Al[391 * 8 * 10240];

// prepacked weights: per ktile: 256 n-rows x 80B = 20480 B (bf16 hi/lo planes)
__device__ __align__(16) unsigned char g_Wfc_h[32 * 20480];
__device__ __align__(16) unsigned char g_Wfc_l[32 * 20480];
__device__ __align__(16) unsigned char g_W1_h[8 * 20480];
__device__ __align__(16) unsigned char g_W1_l[8 * 20480];
__device__ __align__(16) unsigned char g_W2_h[8 * 20480];
__device__ __align__(16) unsigned char g_W2_l[8 * 20480];
__device__ __align__(16) unsigned char g_W3_h[8 * 20480];
__device__ __align__(16) unsigned char g_W3_l[8 * 20480];

// ================= helpers =================
__device__ __forceinline__ uint32_t smem_to_u32(const void* p) {
    uint32_t a;
    asm("{ .reg .u64 t; cvta.to.shared.u64 t, %1; cvt.u32.u64 %0, t; }" : "=r"(a) : "l"(p));
    return a;
}
__device__ __forceinline__ void ldm4(uint32_t* r, uint32_t addr) {
    asm volatile("ldmatrix.sync.aligned.m8n8.x4.shared.b16 {%0,%1,%2,%3}, [%4];"
        : "=r"(r[0]), "=r"(r[1]), "=r"(r[2]), "=r"(r[3]) : "r"(addr));
}
__device__ __forceinline__ void mma_bf16(float* d, const uint32_t* a, const uint32_t* b) {
    asm volatile(
        "mma.sync.aligned.m16n8k16.row.col.f32.bf16.bf16.f32 "
        "{%0,%1,%2,%3}, {%4,%5,%6,%7}, {%8,%9}, {%0,%1,%2,%3};"
        : "+f"(d[0]), "+f"(d[1]), "+f"(d[2]), "+f"(d[3])
        : "r"(a[0]), "r"(a[1]), "r"(a[2]), "r"(a[3]), "r"(b[0]), "r"(b[1]));
}
__device__ __forceinline__ void cp16(uint32_t saddr, const void* gaddr) {
    asm volatile("cp.async.cg.shared.global [%0], [%1], 16;" :: "r"(saddr), "l"(gaddr));
}
#define CP_COMMIT() asm volatile("cp.async.commit_group;" ::: "memory")
#define CP_WAIT0()  asm volatile("cp.async.wait_group 0;" ::: "memory")

__device__ __forceinline__ void split2(float x0, float x1, uint32_t& ph, uint32_t& pl) {
    __nv_bfloat16 h0 = __float2bfloat16(x0), h1 = __float2bfloat16(x1);
    float r0 = x0 - __bfloat162float(h0), r1 = x1 - __bfloat162float(h1);
    __nv_bfloat16 l0 = __float2bfloat16(r0), l1 = __float2bfloat16(r1);
    ph = ((uint32_t)__bfloat16_as_ushort(h1) << 16) | (uint32_t)__bfloat16_as_ushort(h0);
    pl = ((uint32_t)__bfloat16_as_ushort(l1) << 16) | (uint32_t)__bfloat16_as_ushort(l0);
}

// FMA-pipe exp for x <= 0 (magic-number exp2 + degree-5 poly)
__device__ __forceinline__ float fexp_neg(float x) {
    float z = fmaxf(x * 1.44269504f, -126.0f);
    float t = z + 12582912.0f;
    float n = t - 12582912.0f;
    float f = z - n;
    int   i = __float_as_int(t);
    float p = 1.3333558146e-3f;
    p = fmaf(p, f, 9.6181291076e-3f);
    p = fmaf(p, f, 5.5504108664e-2f);
    p = fmaf(p, f, 2.4022650696e-1f);
    p = fmaf(p, f, 6.9314718056e-1f);
    p = fmaf(p, f, 1.0f);
    float s = __int_as_float((((i & 0x7FFFFF) - 0x400000 + 127) << 23));
    return p * s;
}

// interleaved 12-MMA block (same per-acc product order; revisit distance 4)
#define MMA_BLOCK(accp, ah, al, rh, rl, np)                     \
    do {                                                        \
        mma_bf16(accp[0][(np)*2 + 0], ah[0], rh + 0);           \
        mma_bf16(accp[1][(np)*2 + 0], ah[1], rh + 0);           \
        mma_bf16(accp[0][(np)*2 + 1], ah[0], rh + 2);           \
        mma_bf16(accp[1][(np)*2 + 1], ah[1], rh + 2);           \
        mma_bf16(accp[0][(np)*2 + 0], ah[0], rl + 0);           \
        mma_bf16(accp[1][(np)*2 + 0], ah[1], rl + 0);           \
        mma_bf16(accp[0][(np)*2 + 1], ah[0], rl + 2);           \
        mma_bf16(accp[1][(np)*2 + 1], ah[1], rl + 2);           \
        mma_bf16(accp[0][(np)*2 + 0], al[0], rh + 0);           \
        mma_bf16(accp[1][(np)*2 + 0], al[1], rh + 0);           \
        mma_bf16(accp[0][(np)*2 + 1], al[0], rh + 2);           \
        mma_bf16(accp[1][(np)*2 + 1], al[1], rh + 2);           \
    } while (0)

// ---------------- graph prep ----------------
__global__ void k_zero_prep() {
    int i = blockIdx.x * 256 + threadIdx.x;
    if (i < NN) { g_degout[i] = 0; g_degin[i] = 0; g_fill[i] = 0; }
}
__global__ void k_count(const int* __restrict__ src, const int* __restrict__ dst) {
    int e = blockIdx.x * 256 + threadIdx.x;
    if (e < EE) { atomicAdd(&g_degout[src[e]], 1); atomicAdd(&g_degin[dst[e]], 1); }
}
__global__ void k_norms() {
    int i = blockIdx.x * 256 + threadIdx.x;
    if (i < NN) {
        g_ns[i] = rsqrtf((float)max(g_degout[i], 1));
        g_nd[i] = rsqrtf((float)max(g_degin[i], 1));
    }
}
__global__ void k_scan1() {
    __shared__ int s[1024];
    int tid = threadIdx.x;
    int i = blockIdx.x * 1024 + tid;
    int v = (i < NN) ? g_degin[i] : 0;
    s[tid] = v;
    __syncthreads();
    for (int off = 1; off < 1024; off <<= 1) {
        int t = (tid >= off) ? s[tid - off] : 0;
        __syncthreads(); s[tid] += t; __syncthreads();
    }
    g_incl[i] = s[tid];
    if (tid == 1023) g_bsum[blockIdx.x] = s[1023];
}
__global__ void k_scan2() {
    __shared__ int s[64];
    int tid = threadIdx.x;
    int v = (tid < 49) ? g_bsum[tid] : 0;
    s[tid] = v;
    __syncthreads();
    for (int off = 1; off < 64; off <<= 1) {
        int t = (tid >= off) ? s[tid - off] : 0;
        __syncthreads(); s[tid] += t; __syncthreads();
    }
    g_boff[tid] = s[tid] - v;
}
__global__ void k_scan3() {
    int i = blockIdx.x * 256 + threadIdx.x;
    if (i < NN) g_rowptr[i + 1] = g_incl[i] + g_boff[i >> 10];
    if (i == 0) g_rowptr[0] = 0;
}
__global__ void k_fill(const int* __restrict__ src, const int* __restrict__ dst) {
    int e = blockIdx.x * 256 + threadIdx.x;
    if (e < EE) {
        int d = dst[e];
        int pos = g_rowptr[d] + atomicAdd(&g_fill[d], 1);
        g_col[pos] = src[e];
    }
}

// ---------------- SpMM gather (fp16 X) -> packed split-bf16 planes (norm_d fused) ----------------
__global__ void k_spmm(const __half* __restrict__ X) {
    int node = blockIdx.x * 8 + threadIdx.y;
    if (node >= NN) return;
    int lane = threadIdx.x;
    float acc[8];
    #pragma unroll
    for (int i = 0; i < 8; i++) acc[i] = 0.f;

    int beg = g_rowptr[node], end = g_rowptr[node + 1];
    int e = beg;
    for (; e + 1 < end; e += 2) {
        int s0 = g_col[e], s1 = g_col[e + 1];
        float w0 = g_ns[s0], w1 = g_ns[s1];
        uint4 u0 = *(const uint4*)(X + (size_t)s0 * DD + lane * 8);
        uint4 u1 = *(const uint4*)(X + (size_t)s1 * DD + lane * 8);
        const __half2* h0 = (const __half2*)&u0;
        const __half2* h1 = (const __half2*)&u1;
        #pragma unroll
        for (int q = 0; q < 4; q++) {
            float2 f0 = __half22float2(h0[q]);
            float2 f1 = __half22float2(h1[q]);
            acc[q * 2 + 0] += w0 * f0.x + w1 * f1.x;
            acc[q * 2 + 1] += w0 * f0.y + w1 * f1.y;
        }
    }
    if (e < end) {
        int s0 = g_col[e];
        float w0 = g_ns[s0];
        uint4 u0 = *(const uint4*)(X + (size_t)s0 * DD + lane * 8);
        const __half2* h0 = (const __half2*)&u0;
        #pragma unroll
        for (int q = 0; q < 4; q++) {
            float2 f0 = __half22float2(h0[q]);
            acc[q * 2 + 0] += w0 * f0.x;
            acc[q * 2 + 1] += w0 * f0.y;
        }
    }
    float nd = g_nd[node];
    #pragma unroll
    for (int i = 0; i < 8; i++) acc[i] *= nd;

    uint4 vh, vl;
    split2(acc[0], acc[1], vh.x, vl.x);
    split2(acc[2], acc[3], vh.y, vl.y);
    split2(acc[4], acc[5], vh.z, vl.z);
    split2(acc[6], acc[7], vh.w, vl.w);
    size_t base = ((size_t)(node >> 7) * 8 + (lane >> 2)) * 10240
                + (uint32_t)((node & 127) * AB_PITCH + (lane & 3) * 16);
    *(uint4*)(g_Ah + base) = vh;
    *(uint4*)(g_Al + base) = vl;
}

// ---------------- weight prepack (bf16 split) ----------------
__global__ void k_prepack(const float* __restrict__ W, unsigned char* __restrict__ ph,
                          unsigned char* __restrict__ pl, int K) {
    int task = blockIdx.x * 256 + threadIdx.x;
    int nk8 = K >> 3;
    if (task >= DD * nk8) return;
    int n = task / nk8, k8 = task % nk8;
    int k0 = k8 << 3;
    float x[8];
    #pragma unroll
    for (int i = 0; i < 8; i++) x[i] = W[(size_t)(k0 + i) * DD + n];
    uint4 vh, vl;
    split2(x[0], x[1], vh.x, vl.x);
    split2(x[2], x[3], vh.y, vl.y);
    split2(x[4], x[5], vh.z, vl.z);
    split2(x[6], x[7], vh.w, vl.w);
    size_t off = (size_t)(k0 >> 5) * 20480 + (size_t)n * AB_PITCH + (k0 & 31) * 2;
    *(uint4*)(ph + off) = vh;
    *(uint4*)(pl + off) = vl;
}

// ================= 64x128 HMMA GEMM cores (bf16 3-product, 3 CTAs/SM) =================
// CTA 64x128, 256 thr, warps 2x4, warp tile 32x32; gridDim.y = n-half
// buffer 30720: Ah@0(5120) Al@5120 Bh@10240(10240) Bl@20480(10240); x2 buffers
#define SM_AL_OFF 5120
#define SM_BH_OFF 10240
#define SM_BL_OFF 20480
#define BUF_SZ 30720
#define SMEM_GEMM 61440

// ---- fc: fp32 A split on the fly; writes fp16 X ----
__global__ void __launch_bounds__(256, 3) hmma_gemm_fc(
    const float* __restrict__ A,
    const unsigned char* __restrict__ Bh_g, const unsigned char* __restrict__ Bl_g,
    const float* __restrict__ bias, __half* __restrict__ C, int M, int K)
{
    extern __shared__ __align__(16) unsigned char smem[];
    uint32_t sb = smem_to_u32(smem);
    int tid = threadIdx.x;
    int wid = tid >> 5, lane = tid & 31;
    int bm0 = blockIdx.x * 64;
    int nb = blockIdx.y;                    // n-half: cols [nb*128, nb*128+128)
    int nIter = K >> 5;

    int arow = tid >> 2;
    int akq = (tid & 3) * 8;
    int agr = bm0 + arow;
    bool avalid = (agr < M);
    const float* aptr = A + (size_t)(avalid ? agr : 0) * K + akq;
    uint32_t a_soff = (uint32_t)(arow * AB_PITCH + akq * 2);

    int wr = wid >> 2, wc = wid & 3;        // 2 x 4 warps, warp tile 32x32
    int mbase_w = wr * 32;
    int nbase_w = wc * 32;

    int lj = lane >> 3, lr = lane & 7;
    uint32_t aoffA = (uint32_t)(((lj & 1) * 8 + lr) * AB_PITCH + (lj >> 1) * 16);
    uint32_t aoffB = (uint32_t)(((lj >> 1) * 8 + lr) * AB_PITCH + (lj & 1) * 16);

    float acc[2][4][4];
    #pragma unroll
    for (int mt = 0; mt < 2; mt++)
        #pragma unroll
        for (int nt = 0; nt < 4; nt++)
            #pragma unroll
            for (int i = 0; i < 4; i++) acc[mt][nt][i] = 0.f;

    {
        size_t tb = (size_t)nb * 10240;
        for (int c = tid; c < 640; c += 256) {
            cp16(sb + SM_BH_OFF + c * 16, Bh_g + tb + c * 16);
            cp16(sb + SM_BL_OFF + c * 16, Bl_g + tb + c * 16);
        }
        CP_COMMIT();
        float4 v0 = make_float4(0.f, 0.f, 0.f, 0.f), v1 = v0;
        if (avalid) { v0 = *(const float4*)(aptr); v1 = *(const float4*)(aptr + 4); }
        uint4 vh, vl;
        split2(v0.x, v0.y, vh.x, vl.x);
        split2(v0.z, v0.w, vh.y, vl.y);
        split2(v1.x, v1.y, vh.z, vl.z);
        split2(v1.z, v1.w, vh.w, vl.w);
        *(uint4*)(smem + a_soff) = vh;
        *(uint4*)(smem + SM_AL_OFF + a_soff) = vl;
        CP_WAIT0();
        __syncthreads();
    }

    for (int it = 0; it < nIter; it++) {
        uint32_t bufo = (uint32_t)((it & 1) * BUF_SZ);
        uint32_t nbufo = (uint32_t)(((it + 1) & 1) * BUF_SZ);
        bool more = (it + 1 < nIter);

        float4 v0 = make_float4(0.f, 0.f, 0.f, 0.f), v1 = v0;
        if (more) {
            size_t tb = (size_t)(it + 1) * 20480 + (size_t)nb * 10240;
            for (int c = tid; c < 640; c += 256) {
                cp16(sb + nbufo + SM_BH_OFF + c * 16, Bh_g + tb + c * 16);
                cp16(sb + nbufo + SM_BL_OFF + c * 16, Bl_g + tb + c * 16);
            }
            CP_COMMIT();
            if (avalid) {
                int k0 = (it + 1) << 5;
                v0 = *(const float4*)(aptr + k0);
                v1 = *(const float4*)(aptr + k0 + 4);
            }
        }

        #pragma unroll
        for (int ks = 0; ks < 2; ks++) {
            uint32_t kof = (uint32_t)(ks * 32);
            uint32_t ah[2][4], al[2][4];
            #pragma unroll
            for (int mt = 0; mt < 2; mt++) {
                uint32_t base = sb + bufo + (uint32_t)((mbase_w + mt * 16) * AB_PITCH) + kof + aoffA;
                ldm4(ah[mt], base);
                ldm4(al[mt], base + SM_AL_OFF);
            }
            #pragma unroll
            for (int np = 0; np < 2; np++) {
                uint32_t bbase = sb + bufo + SM_BH_OFF + (uint32_t)((nbase_w + np * 16) * AB_PITCH) + kof + aoffB;
                uint32_t rh[4], rl[4];
                ldm4(rh, bbase);
                ldm4(rl, bbase + 10240);
                MMA_BLOCK(acc, ah, al, rh, rl, np);
            }
        }

        if (more) {
            uint4 vh, vl;
            split2(v0.x, v0.y, vh.x, vl.x);
            split2(v0.z, v0.w, vh.y, vl.y);
            split2(v1.x, v1.y, vh.z, vl.z);
            split2(v1.z, v1.w, vh.w, vl.w);
            *(uint4*)(smem + nbufo + a_soff) = vh;
            *(uint4*)(smem + nbufo + SM_AL_OFF + a_soff) = vl;
            CP_WAIT0();
        }
        __syncthreads();
    }

    int g = lane >> 2, t2 = (lane & 3) * 2;
    #pragma unroll
    for (int mt = 0; mt < 2; mt++) {
        int r0 = bm0 + mbase_w + mt * 16 + g;
        int r1 = r0 + 8;
        #pragma unroll
        for (int nt = 0; nt < 4; nt++) {
            int c = nb * 128 + nbase_w + nt * 8 + t2;
            float b0 = __ldg(&bias[c]), b1 = __ldg(&bias[c + 1]);
            if (r0 < M) *(__half2*)(C + (size_t)r0 * DD + c) =
                __floats2half2_rn(acc[mt][nt][0] + b0, acc[mt][nt][1] + b1);
            if (r1 < M) *(__half2*)(C + (size_t)r1 * DD + c) =
                __floats2half2_rn(acc[mt][nt][2] + b0, acc[mt][nt][3] + b1);
        }
    }
}

// ---- layer GEMM: packed split-bf16 A; output fp16 (layers 1,2) or fp32 (layer 3) ----
template <bool HALF_OUT>
__global__ void __launch_bounds__(256, 3) hmma_gemm_pk(
    const unsigned char* __restrict__ Ah_g, const unsigned char* __restrict__ Al_g,
    const unsigned char* __restrict__ Bh_g, const unsigned char* __restrict__ Bl_g,
    const float* __restrict__ bias, void* __restrict__ Cv, int M)
{
    extern __shared__ __align__(16) unsigned char smem[];
    uint32_t sb = smem_to_u32(smem);
    int tid = threadIdx.x;
    int wid = tid >> 5, lane = tid & 31;
    int bm0 = blockIdx.x * 64;
    int nb = blockIdx.y;
    const int nIter = 8;
    size_t abase = (size_t)(blockIdx.x >> 1) * 8 * 10240 + (size_t)(blockIdx.x & 1) * 5120;

    int wr = wid >> 2, wc = wid & 3;
    int mbase_w = wr * 32;
    int nbase_w = wc * 32;

    int lj = lane >> 3, lr = lane & 7;
    uint32_t aoffA = (uint32_t)(((lj & 1) * 8 + lr) * AB_PITCH + (lj >> 1) * 16);
    uint32_t aoffB = (uint32_t)(((lj >> 1) * 8 + lr) * AB_PITCH + (lj & 1) * 16);

    float acc[2][4][4];
    #pragma unroll
    for (int mt = 0; mt < 2; mt++)
        #pragma unroll
        for (int nt = 0; nt < 4; nt++)
            #pragma unroll
            for (int i = 0; i < 4; i++) acc[mt][nt][i] = 0.f;

    {
        size_t tb = (size_t)nb * 10240;
        for (int c = tid; c < 320; c += 256) {
            cp16(sb + c * 16, Ah_g + abase + c * 16);
            cp16(sb + SM_AL_OFF + c * 16, Al_g + abase + c * 16);
        }
        for (int c = tid; c < 640; c += 256) {
            cp16(sb + SM_BH_OFF + c * 16, Bh_g + tb + c * 16);
            cp16(sb + SM_BL_OFF + c * 16, Bl_g + tb + c * 16);
        }
        CP_COMMIT();
        CP_WAIT0();
        __syncthreads();
    }

    for (int it = 0; it < nIter; it++) {
        uint32_t bufo = (uint32_t)((it & 1) * BUF_SZ);
        uint32_t nbufo = (uint32_t)(((it + 1) & 1) * BUF_SZ);
        bool more = (it + 1 < nIter);

        if (more) {
            size_t ta = abase + (size_t)(it + 1) * 10240;
            size_t tb = (size_t)(it + 1) * 20480 + (size_t)nb * 10240;
            for (int c = tid; c < 320; c += 256) {
                cp16(sb + nbufo + c * 16, Ah_g + ta + c * 16);
                cp16(sb + nbufo + SM_AL_OFF + c * 16, Al_g + ta + c * 16);
            }
            for (int c = tid; c < 640; c += 256) {
                cp16(sb + nbufo + SM_BH_OFF + c * 16, Bh_g + tb + c * 16);
                cp16(sb + nbufo + SM_BL_OFF + c * 16, Bl_g + tb + c * 16);
            }
            CP_COMMIT();
        }

        #pragma unroll
        for (int ks = 0; ks < 2; ks++) {
            uint32_t kof = (uint32_t)(ks * 32);
            uint32_t ah[2][4], al[2][4];
            #pragma unroll
            for (int mt = 0; mt < 2; mt++) {
                uint32_t base = sb + bufo + (uint32_t)((mbase_w + mt * 16) * AB_PITCH) + kof + aoffA;
                ldm4(ah[mt], base);
                ldm4(al[mt], base + SM_AL_OFF);
            }
            #pragma unroll
            for (int np = 0; np < 2; np++) {
                uint32_t bbase = sb + bufo + SM_BH_OFF + (uint32_t)((nbase_w + np * 16) * AB_PITCH) + kof + aoffB;
                uint32_t rh[4], rl[4];
                ldm4(rh, bbase);
                ldm4(rl, bbase + 10240);
                MMA_BLOCK(acc, ah, al, rh, rl, np);
            }
        }

        if (more) CP_WAIT0();
        __syncthreads();
    }

    int g = lane >> 2, t2 = (lane & 3) * 2;
    #pragma unroll
    for (int mt = 0; mt < 2; mt++) {
        int r0 = bm0 + mbase_w + mt * 16 + g;
        int r1 = r0 + 8;
        #pragma unroll
        for (int nt = 0; nt < 4; nt++) {
            int c = nb * 128 + nbase_w + nt * 8 + t2;
            float b0 = __ldg(&bias[c]), b1 = __ldg(&bias[c + 1]);
            if (HALF_OUT) {
                __half* C = (__half*)Cv;
                if (r0 < M) *(__half2*)(C + (size_t)r0 * DD + c) =
                    __floats2half2_rn(acc[mt][nt][0] + b0, acc[mt][nt][1] + b1);
                if (r1 < M) *(__half2*)(C + (size_t)r1 * DD + c) =
                    __floats2half2_rn(acc[mt][nt][2] + b0, acc[mt][nt][3] + b1);
            } else {
                float* C = (float*)Cv;
                if (r0 < M) *(float2*)(C + (size_t)r0 * DD + c) =
                    make_float2(acc[mt][nt][0] + b0, acc[mt][nt][1] + b1);
                if (r1 < M) *(float2*)(C + (size_t)r1 * DD + c) =
                    make_float2(acc[mt][nt][2] + b0, acc[mt][nt][3] + b1);
            }
        }
    }
}

// ---------------- BatchNorm + ELU (fp16 X) ----------------
__global__ void k_zero_bn() {
    int c = threadIdx.x;
    g_bns[c] = 0.f;
    g_bnq[c] = 0.f;
}
__global__ void k_bn_stats(const __half* __restrict__ X) {
    int c = threadIdx.x;
    int r0 = blockIdx.x * 256;
    int r1 = min(r0 + 256, NN);
    float s = 0.f, q = 0.f;
    for (int r = r0; r < r1; r++) {
        float v = __half2float(X[(size_t)r * DD + c]);
        s += v; q += v * v;
    }
    atomicAdd(&g_bns[c], s);
    atomicAdd(&g_bnq[c], q);
}
__global__ void k_bn_apply(__half* __restrict__ X,
                           const float* __restrict__ gamma,
                           const float* __restrict__ beta) {
    int idx = blockIdx.x * 256 + threadIdx.x;
    if (idx >= NN * (DD / 2)) return;
    int c2 = idx & 127;
    int c = c2 * 2;
    const float invN = 1.f / (float)NN;
    float2 sm = *(const float2*)&g_bns[c];
    float2 sq = *(const float2*)&g_bnq[c];
    float2 gm = *(const float2*)&gamma[c];
    float2 bt = *(const float2*)&beta[c];
    __half2 hx = ((__half2*)X)[idx];
    float2 x = __half22float2(hx);
    float mu, var, sc;
    float2 y;
    mu = sm.x * invN; var = sq.x * invN - mu * mu; sc = gm.x * rsqrtf(var + 1e-5f);
    y.x = sc * (x.x - mu) + bt.x;
    mu = sm.y * invN; var = sq.y * invN - mu * mu; sc = gm.y * rsqrtf(var + 1e-5f);
    y.y = sc * (x.y - mu) + bt.y;
    y.x = (y.x > 0.f) ? y.x : (__expf(y.x) - 1.f);
    y.y = (y.y > 0.f) ? y.y : (fexp_neg(y.y) - 1.f);
    ((__half2*)X)[idx] = __floats2half2_rn(y.x, y.y);
}

// ---------------- logits GEMM (reads fp32 out) ----------------
__global__ __launch_bounds__(320) void k_logits(
    const float* __restrict__ X, const float* __restrict__ W,
    const float* __restrict__ bias, float* __restrict__ O, int M)
{
    __shared__ float Xs[32][68];
    __shared__ float Ws[32][40];
    int tid = threadIdx.x;
    int bm0 = blockIdx.x * 64;
    int rg = tid / 40;
    int col = tid % 40;
    float acc[8];
    #pragma unroll
    for (int i = 0; i < 8; i++) acc[i] = 0.f;

    for (int k0 = 0; k0 < DD; k0 += 32) {
        for (int idx = tid; idx < 512; idx += 320) {
            int row = idx >> 3;
            int kq = idx & 7;
            float4 v = make_float4(0.f, 0.f, 0.f, 0.f);
            int gr = bm0 + row;
            if (gr < M) v = *(const float4*)(X + (size_t)gr * DD + k0 + kq * 4);
            Xs[kq * 4 + 0][row] = v.x;
            Xs[kq * 4 + 1][row] = v.y;
            Xs[kq * 4 + 2][row] = v.z;
            Xs[kq * 4 + 3][row] = v.w;
        }
        for (int idx = tid; idx < 1280; idx += 320) {
            int k = idx / 40, c = idx % 40;
            Ws[k][c] = W[(size_t)(k0 + k) * CC + c];
        }
        __syncthreads();
        #pragma unroll
        for (int kk = 0; kk < 32; kk++) {
            float w = Ws[kk][col];
            float a0[4], a1[4];
            *(float4*)&a0[0] = *(float4*)&Xs[kk][rg * 8];
            *(float4*)&a1[0] = *(float4*)&Xs[kk][rg * 8 + 4];
            acc[0] += a0[0] * w; acc[1] += a0[1] * w;
            acc[2] += a0[2] * w; acc[3] += a0[3] * w;
            acc[4] += a1[0] * w; acc[5] += a1[1] * w;
            acc[6] += a1[2] * w; acc[7] += a1[3] * w;
        }
        __syncthreads();
    }
    float b = bias[col];
    #pragma unroll
    for (int i = 0; i < 8; i++) {
        int r = bm0 + rg * 8 + i;
        if (r < M) O[(size_t)r * CC + col] = acc[i] + b;
    }
}

// ---------------- static stream/event init ----------------
struct SideRes {
    cudaStream_t sB;
    cudaEvent_t evFork, evJoin;
    SideRes() {
        cudaStreamCreateWithFlags(&sB, cudaStreamNonBlocking);
        cudaEventCreateWithFlags(&evFork, cudaEventDisableTiming);
        cudaEventCreateWithFlags(&evJoin, cudaEventDisableTiming);
        cudaFuncSetAttribute(hmma_gemm_fc, cudaFuncAttributeMaxDynamicSharedMemorySize, SMEM_GEMM);
        cudaFuncSetAttribute(hmma_gemm_pk<true>,  cudaFuncAttributeMaxDynamicSharedMemorySize, SMEM_GEMM);
        cudaFuncSetAttribute(hmma_gemm_pk<false>, cudaFuncAttributeMaxDynamicSharedMemorySize, SMEM_GEMM);
    }
};
static SideRes g_sr;

// ---------------- driver ----------------
extern "C" void kernel_launch(void* const* d_in, const int* in_sizes, int n_in,
                              void* d_out, int out_size)
{
    const float* feat  = (const float*)d_in[0];
    const int*   src   = (const int*)d_in[1];
    const int*   dst   = (const int*)d_in[2];
    const float* W_fc  = (const float*)d_in[3];
    const float* b_fc  = (const float*)d_in[4];
    const float* W1    = (const float*)d_in[5];
    const float* b1    = (const float*)d_in[6];
    const float* W2    = (const float*)d_in[7];
    const float* b2    = (const float*)d_in[8];
    const float* W3    = (const float*)d_in[9];
    const float* b3    = (const float*)d_in[10];
    const float* gamma = (const float*)d_in[11];
    const float* beta  = (const float*)d_in[12];
    const float* W_lin = (const float*)d_in[13];
    const float* b_lin = (const float*)d_in[14];
    float* out = (float*)d_out;

    __half* gX16; cudaGetSymbolAddress((void**)&gX16, g_X16);
    unsigned char *gAh, *gAl;
    cudaGetSymbolAddress((void**)&gAh, g_Ah);
    cudaGetSymbolAddress((void**)&gAl, g_Al);
    unsigned char *pFh, *pFl, *p1h, *p1l, *p2h, *p2l, *p3h, *p3l;
    cudaGetSymbolAddress((void**)&pFh, g_Wfc_h);
    cudaGetSymbolAddress((void**)&pFl, g_Wfc_l);
    cudaGetSymbolAddress((void**)&p1h, g_W1_h);
    cudaGetSymbolAddress((void**)&p1l, g_W1_l);
    cudaGetSymbolAddress((void**)&p2h, g_W2_h);
    cudaGetSymbolAddress((void**)&p2l, g_W2_l);
    cudaGetSymbolAddress((void**)&p3h, g_W3_h);
    cudaGetSymbolAddress((void**)&p3l, g_W3_l);

    const int NB_N = (NN + 255) / 256;
    const int NB_E = (EE + 255) / 256;
    dim3 gemm_grid((NN + 63) / 64, 2);     // 782 x 2 n-halves
    dim3 spmm_block(32, 8);
    int spmm_grid = (NN + 7) / 8;
    int bn_grid = (NN * (DD / 2) + 255) / 256;

    // fork
    cudaEventRecord(g_sr.evFork, 0);
    cudaStreamWaitEvent(g_sr.sB, g_sr.evFork, 0);

    k_zero_prep<<<NB_N, 256, 0, g_sr.sB>>>();
    k_count<<<NB_E, 256, 0, g_sr.sB>>>(src, dst);
    k_prepack<<<(DD * (FF / 8) + 255) / 256, 256>>>(W_fc, pFh, pFl, FF);              // main
    hmma_gemm_fc<<<gemm_grid, 256, SMEM_GEMM>>>(feat, pFh, pFl, b_fc, gX16, NN, FF);  // main
    k_norms<<<NB_N, 256, 0, g_sr.sB>>>();
    k_scan1<<<49, 1024, 0, g_sr.sB>>>();
    k_scan2<<<1, 64, 0, g_sr.sB>>>();
    k_scan3<<<NB_N, 256, 0, g_sr.sB>>>();
    k_fill<<<NB_E, 256, 0, g_sr.sB>>>(src, dst);
    k_prepack<<<(DD * (DD / 8) + 255) / 256, 256, 0, g_sr.sB>>>(W1, p1h, p1l, DD);
    k_prepack<<<(DD * (DD / 8) + 255) / 256, 256, 0, g_sr.sB>>>(W2, p2h, p2l, DD);
    k_prepack<<<(DD * (DD / 8) + 255) / 256, 256, 0, g_sr.sB>>>(W3, p3h, p3l, DD);
    k_zero_bn<<<1, 256, 0, g_sr.sB>>>();
    cudaEventRecord(g_sr.evJoin, g_sr.sB);

    // join
    cudaStreamWaitEvent(0, g_sr.evJoin, 0);

    // layer 1
    k_spmm<<<spmm_grid, spmm_block>>>(gX16);
    hmma_gemm_pk<true><<<gemm_grid, 256, SMEM_GEMM>>>(gAh, gAl, p1h, p1l, b1, gX16, NN);
    k_bn_stats<<<NB_N, 256>>>(gX16);
    k_bn_apply<<<bn_grid, 256>>>(gX16, gamma, beta);
    k_zero_bn<<<1, 256>>>();

    // layer 2
    k_spmm<<<spmm_grid, spmm_block>>>(gX16);
    hmma_gemm_pk<true><<<gemm_grid, 256, SMEM_GEMM>>>(gAh, gAl, p2h, p2l, b2, gX16, NN);
    k_bn_stats<<<NB_N, 256>>>(gX16);
    k_bn_apply<<<bn_grid, 256>>>(gX16, gamma, beta);

    // layer 3 -> fp32 features into d_out[0 : N*D)
    k_spmm<<<spmm_grid, spmm_block>>>(gX16);
    hmma_gemm_pk<false><<<gemm_grid, 256, SMEM_GEMM>>>(gAh, gAl, p3h, p3l, b3, out, NN);

    // logits -> d_out[N*D : )
    k_logits<<<(NN + 63) / 64, 320>>>(out, W_lin, b_lin, out + (size_t)NN * DD, NN);
}

// round 15
// speedup vs baseline: 1.0458x; 1.0248x over previous
#include <cuda_runtime.h>
#include <cuda_bf16.h>
#include <cuda_fp16.h>
#include <math.h>
#include <stdint.h>

#define NN 50000
#define EE 300000
#define DD 256
#define FF 1024
#define CC 40
#define AB_PITCH 80

// row-split: half0 = rows [0, 25024), half1 = rows [25024, 50000)
#define H0_NODES 25024
#define RB_HALF 391     // 64-row blocks per half

// ---------------- scratch (static device globals; no allocation) ----------------
__device__ __half g_Xa[NN * DD];        // activation ping
__device__ __half g_Xb[NN * DD];        // activation pong
__device__ float g_ns[NN];
__device__ float g_nd[NN];
__device__ int   g_degout[NN];
__device__ int   g_degin[NN];
__device__ int   g_fill[NN];
__device__ int   g_incl[49 * 1024];
__device__ int   g_bsum[64];
__device__ int   g_boff[64];
__device__ int   g_rowptr[NN + 1];
__device__ int   g_col[EE];
__device__ float g_bns[DD];
__device__ float g_bnq[DD];

__device__ __align__(16) unsigned char g_Ah[391 * 8 * 10240];
__device__ __align__(16) unsigned char g_Al[391 * 8 * 10240];

__device__ __align__(16) unsigned char g_Wfc_h[32 * 20480];
__device__ __align__(16) unsigned char g_Wfc_l[32 * 20480];
__device__ __align__(16) unsigned char g_W1_h[8 * 20480];
__device__ __align__(16) unsigned char g_W1_l[8 * 20480];
__device__ __align__(16) unsigned char g_W2_h[8 * 20480];
__device__ __align__(16) unsigned char g_W2_l[8 * 20480];
__device__ __align__(16) unsigned char g_W3_h[8 * 20480];
__device__ __align__(16) unsigned char g_W3_l[8 * 20480];

// ================= helpers =================
__device__ __forceinline__ uint32_t smem_to_u32(const void* p) {
    uint32_t a;
    asm("{ .reg .u64 t; cvta.to.shared.u64 t, %1; cvt.u32.u64 %0, t; }" : "=r"(a) : "l"(p));
    return a;
}
__device__ __forceinline__ void ldm4(uint32_t* r, uint32_t addr) {
    asm volatile("ldmatrix.sync.aligned.m8n8.x4.shared.b16 {%0,%1,%2,%3}, [%4];"
        : "=r"(r[0]), "=r"(r[1]), "=r"(r[2]), "=r"(r[3]) : "r"(addr));
}
__device__ __forceinline__ void mma_bf16(float* d, const uint32_t* a, const uint32_t* b) {
    asm volatile(
        "mma.sync.aligned.m16n8k16.row.col.f32.bf16.bf16.f32 "
        "{%0,%1,%2,%3}, {%4,%5,%6,%7}, {%8,%9}, {%0,%1,%2,%3};"
        : "+f"(d[0]), "+f"(d[1]), "+f"(d[2]), "+f"(d[3])
        : "r"(a[0]), "r"(a[1]), "r"(a[2]), "r"(a[3]), "r"(b[0]), "r"(b[1]));
}
__device__ __forceinline__ void cp16(uint32_t saddr, const void* gaddr) {
    asm volatile("cp.async.cg.shared.global [%0], [%1], 16;" :: "r"(saddr), "l"(gaddr));
}
#define CP_COMMIT() asm volatile("cp.async.commit_group;" ::: "memory")
#define CP_WAIT0()  asm volatile("cp.async.wait_group 0;" ::: "memory")

__device__ __forceinline__ void split2(float x0, float x1, uint32_t& ph, uint32_t& pl) {
    __nv_bfloat16 h0 = __float2bfloat16(x0), h1 = __float2bfloat16(x1);
    float r0 = x0 - __bfloat162float(h0), r1 = x1 - __bfloat162float(h1);
    __nv_bfloat16 l0 = __float2bfloat16(r0), l1 = __float2bfloat16(r1);
    ph = ((uint32_t)__bfloat16_as_ushort(h1) << 16) | (uint32_t)__bfloat16_as_ushort(h0);
    pl = ((uint32_t)__bfloat16_as_ushort(l1) << 16) | (uint32_t)__bfloat16_as_ushort(l0);
}

__device__ __forceinline__ float fexp_neg(float x) {
    float z = fmaxf(x * 1.44269504f, -126.0f);
    float t = z + 12582912.0f;
    float n = t - 12582912.0f;
    float f = z - n;
    int   i = __float_as_int(t);
    float p = 1.3333558146e-3f;
    p = fmaf(p, f, 9.6181291076e-3f);
    p = fmaf(p, f, 5.5504108664e-2f);
    p = fmaf(p, f, 2.4022650696e-1f);
    p = fmaf(p, f, 6.9314718056e-1f);
    p = fmaf(p, f, 1.0f);
    float s = __int_as_float((((i & 0x7FFFFF) - 0x400000 + 127) << 23));
    return p * s;
}

#define MMA_BLOCK(accp, ah, al, rh, rl, np)                     \
    do {                                                        \
        mma_bf16(accp[0][(np)*2 + 0], ah[0], rh + 0);           \
        mma_bf16(accp[1][(np)*2 + 0], ah[1], rh + 0);           \
        mma_bf16(accp[0][(np)*2 + 1], ah[0], rh + 2);           \
        mma_bf16(accp[1][(np)*2 + 1], ah[1], rh + 2);           \
        mma_bf16(accp[0][(np)*2 + 0], ah[0], rl + 0);           \
        mma_bf16(accp[1][(np)*2 + 0], ah[1], rl + 0);           \
        mma_bf16(accp[0][(np)*2 + 1], ah[0], rl + 2);           \
        mma_bf16(accp[1][(np)*2 + 1], ah[1], rl + 2);           \
        mma_bf16(accp[0][(np)*2 + 0], al[0], rh + 0);           \
        mma_bf16(accp[1][(np)*2 + 0], al[1], rh + 0);           \
        mma_bf16(accp[0][(np)*2 + 1], al[0], rh + 2);           \
        mma_bf16(accp[1][(np)*2 + 1], al[1], rh + 2);           \
    } while (0)

// ---------------- graph prep ----------------
__global__ void k_zero_prep() {
    int i = blockIdx.x * 256 + threadIdx.x;
    if (i < NN) { g_degout[i] = 0; g_degin[i] = 0; g_fill[i] = 0; }
}
__global__ void k_count(const int* __restrict__ src, const int* __restrict__ dst) {
    int e = blockIdx.x * 256 + threadIdx.x;
    if (e < EE) { atomicAdd(&g_degout[src[e]], 1); atomicAdd(&g_degin[dst[e]], 1); }
}
__global__ void k_norms() {
    int i = blockIdx.x * 256 + threadIdx.x;
    if (i < NN) {
        g_ns[i] = rsqrtf((float)max(g_degout[i], 1));
        g_nd[i] = rsqrtf((float)max(g_degin[i], 1));
    }
}
__global__ void k_scan1() {
    __shared__ int s[1024];
    int tid = threadIdx.x;
    int i = blockIdx.x * 1024 + tid;
    int v = (i < NN) ? g_degin[i] : 0;
    s[tid] = v;
    __syncthreads();
    for (int off = 1; off < 1024; off <<= 1) {
        int t = (tid >= off) ? s[tid - off] : 0;
        __syncthreads(); s[tid] += t; __syncthreads();
    }
    g_incl[i] = s[tid];
    if (tid == 1023) g_bsum[blockIdx.x] = s[1023];
}
__global__ void k_scan2() {
    __shared__ int s[64];
    int tid = threadIdx.x;
    int v = (tid < 49) ? g_bsum[tid] : 0;
    s[tid] = v;
    __syncthreads();
    for (int off = 1; off < 64; off <<= 1) {
        int t = (tid >= off) ? s[tid - off] : 0;
        __syncthreads(); s[tid] += t; __syncthreads();
    }
    g_boff[tid] = s[tid] - v;
}
__global__ void k_scan3() {
    int i = blockIdx.x * 256 + threadIdx.x;
    if (i < NN) g_rowptr[i + 1] = g_incl[i] + g_boff[i >> 10];
    if (i == 0) g_rowptr[0] = 0;
}
__global__ void k_fill(const int* __restrict__ src, const int* __restrict__ dst) {
    int e = blockIdx.x * 256 + threadIdx.x;
    if (e < EE) {
        int d = dst[e];
        int pos = g_rowptr[d] + atomicAdd(&g_fill[d], 1);
        g_col[pos] = src[e];
    }
}

// ---------------- SpMM gather (fp16 X) -> packed split-bf16 planes; node_off for row-split ----------------
__global__ void k_spmm(const __half* __restrict__ X, int node_off) {
    int node = node_off + blockIdx.x * 8 + threadIdx.y;
    if (node >= NN) return;
    int lane = threadIdx.x;
    float acc[8];
    #pragma unroll
    for (int i = 0; i < 8; i++) acc[i] = 0.f;

    int beg = g_rowptr[node], end = g_rowptr[node + 1];
    int e = beg;
    for (; e + 1 < end; e += 2) {
        int s0 = g_col[e], s1 = g_col[e + 1];
        float w0 = g_ns[s0], w1 = g_ns[s1];
        uint4 u0 = *(const uint4*)(X + (size_t)s0 * DD + lane * 8);
        uint4 u1 = *(const uint4*)(X + (size_t)s1 * DD + lane * 8);
        const __half2* h0 = (const __half2*)&u0;
        const __half2* h1 = (const __half2*)&u1;
        #pragma unroll
        for (int q = 0; q < 4; q++) {
            float2 f0 = __half22float2(h0[q]);
            float2 f1 = __half22float2(h1[q]);
            acc[q * 2 + 0] += w0 * f0.x + w1 * f1.x;
            acc[q * 2 + 1] += w0 * f0.y + w1 * f1.y;
        }
    }
    if (e < end) {
        int s0 = g_col[e];
        float w0 = g_ns[s0];
        uint4 u0 = *(const uint4*)(X + (size_t)s0 * DD + lane * 8);
        const __half2* h0 = (const __half2*)&u0;
        #pragma unroll
        for (int q = 0; q < 4; q++) {
            float2 f0 = __half22float2(h0[q]);
            acc[q * 2 + 0] += w0 * f0.x;
            acc[q * 2 + 1] += w0 * f0.y;
        }
    }
    float nd = g_nd[node];
    #pragma unroll
    for (int i = 0; i < 8; i++) acc[i] *= nd;

    uint4 vh, vl;
    split2(acc[0], acc[1], vh.x, vl.x);
    split2(acc[2], acc[3], vh.y, vl.y);
    split2(acc[4], acc[5], vh.z, vl.z);
    split2(acc[6], acc[7], vh.w, vl.w);
    size_t base = ((size_t)(node >> 7) * 8 + (lane >> 2)) * 10240
                + (uint32_t)((node & 127) * AB_PITCH + (lane & 3) * 16);
    *(uint4*)(g_Ah + base) = vh;
    *(uint4*)(g_Al + base) = vl;
}

// ---------------- weight prepack (bf16 split) ----------------
__global__ void k_prepack(const float* __restrict__ W, unsigned char* __restrict__ ph,
                          unsigned char* __restrict__ pl, int K) {
    int task = blockIdx.x * 256 + threadIdx.x;
    int nk8 = K >> 3;
    if (task >= DD * nk8) return;
    int n = task / nk8, k8 = task % nk8;
    int k0 = k8 << 3;
    float x[8];
    #pragma unroll
    for (int i = 0; i < 8; i++) x[i] = W[(size_t)(k0 + i) * DD + n];
    uint4 vh, vl;
    split2(x[0], x[1], vh.x, vl.x);
    split2(x[2], x[3], vh.y, vl.y);
    split2(x[4], x[5], vh.z, vl.z);
    split2(x[6], x[7], vh.w, vl.w);
    size_t off = (size_t)(k0 >> 5) * 20480 + (size_t)n * AB_PITCH + (k0 & 31) * 2;
    *(uint4*)(ph + off) = vh;
    *(uint4*)(pl + off) = vl;
}

// ================= 64x128 HMMA GEMM cores (bf16 3-product, 3 CTAs/SM) =================
#define SM_AL_OFF 5120
#define SM_BH_OFF 10240
#define SM_BL_OFF 20480
#define BUF_SZ 30720
#define SMEM_GEMM 61440

// ---- fc: fp32 A split on the fly; writes fp16 X ----
__global__ void __launch_bounds__(256, 3) hmma_gemm_fc(
    const float* __restrict__ A,
    const unsigned char* __restrict__ Bh_g, const unsigned char* __restrict__ Bl_g,
    const float* __restrict__ bias, __half* __restrict__ C, int M, int K)
{
    extern __shared__ __align__(16) unsigned char smem[];
    uint32_t sb = smem_to_u32(smem);
    int tid = threadIdx.x;
    int wid = tid >> 5, lane = tid & 31;
    int bm0 = blockIdx.x * 64;
    int nb = blockIdx.y;
    int nIter = K >> 5;

    int arow = tid >> 2;
    int akq = (tid & 3) * 8;
    int agr = bm0 + arow;
    bool avalid = (agr < M);
    const float* aptr = A + (size_t)(avalid ? agr : 0) * K + akq;
    uint32_t a_soff = (uint32_t)(arow * AB_PITCH + akq * 2);

    int wr = wid >> 2, wc = wid & 3;
    int mbase_w = wr * 32;
    int nbase_w = wc * 32;

    int lj = lane >> 3, lr = lane & 7;
    uint32_t aoffA = (uint32_t)(((lj & 1) * 8 + lr) * AB_PITCH + (lj >> 1) * 16);
    uint32_t aoffB = (uint32_t)(((lj >> 1) * 8 + lr) * AB_PITCH + (lj & 1) * 16);

    float acc[2][4][4];
    #pragma unroll
    for (int mt = 0; mt < 2; mt++)
        #pragma unroll
        for (int nt = 0; nt < 4; nt++)
            #pragma unroll
            for (int i = 0; i < 4; i++) acc[mt][nt][i] = 0.f;

    {
        size_t tb = (size_t)nb * 10240;
        for (int c = tid; c < 640; c += 256) {
            cp16(sb + SM_BH_OFF + c * 16, Bh_g + tb + c * 16);
            cp16(sb + SM_BL_OFF + c * 16, Bl_g + tb + c * 16);
        }
        CP_COMMIT();
        float4 v0 = make_float4(0.f, 0.f, 0.f, 0.f), v1 = v0;
        if (avalid) { v0 = *(const float4*)(aptr); v1 = *(const float4*)(aptr + 4); }
        uint4 vh, vl;
        split2(v0.x, v0.y, vh.x, vl.x);
        split2(v0.z, v0.w, vh.y, vl.y);
        split2(v1.x, v1.y, vh.z, vl.z);
        split2(v1.z, v1.w, vh.w, vl.w);
        *(uint4*)(smem + a_soff) = vh;
        *(uint4*)(smem + SM_AL_OFF + a_soff) = vl;
        CP_WAIT0();
        __syncthreads();
    }

    for (int it = 0; it < nIter; it++) {
        uint32_t bufo = (uint32_t)((it & 1) * BUF_SZ);
        uint32_t nbufo = (uint32_t)(((it + 1) & 1) * BUF_SZ);
        bool more = (it + 1 < nIter);

        float4 v0 = make_float4(0.f, 0.f, 0.f, 0.f), v1 = v0;
        if (more) {
            size_t tb = (size_t)(it + 1) * 20480 + (size_t)nb * 10240;
            for (int c = tid; c < 640; c += 256) {
                cp16(sb + nbufo + SM_BH_OFF + c * 16, Bh_g + tb + c * 16);
                cp16(sb + nbufo + SM_BL_OFF + c * 16, Bl_g + tb + c * 16);
            }
            CP_COMMIT();
            if (avalid) {
                int k0 = (it + 1) << 5;
                v0 = *(const float4*)(aptr + k0);
                v1 = *(const float4*)(aptr + k0 + 4);
            }
        }

        #pragma unroll
        for (int ks = 0; ks < 2; ks++) {
            uint32_t kof = (uint32_t)(ks * 32);
            uint32_t ah[2][4], al[2][4];
            #pragma unroll
            for (int mt = 0; mt < 2; mt++) {
                uint32_t base = sb + bufo + (uint32_t)((mbase_w + mt * 16) * AB_PITCH) + kof + aoffA;
                ldm4(ah[mt], base);
                ldm4(al[mt], base + SM_AL_OFF);
            }
            #pragma unroll
            for (int np = 0; np < 2; np++) {
                uint32_t bbase = sb + bufo + SM_BH_OFF + (uint32_t)((nbase_w + np * 16) * AB_PITCH) + kof + aoffB;
                uint32_t rh[4], rl[4];
                ldm4(rh, bbase);
                ldm4(rl, bbase + 10240);
                MMA_BLOCK(acc, ah, al, rh, rl, np);
            }
        }

        if (more) {
            uint4 vh, vl;
            split2(v0.x, v0.y, vh.x, vl.x);
            split2(v0.z, v0.w, vh.y, vl.y);
            split2(v1.x, v1.y, vh.z, vl.z);
            split2(v1.z, v1.w, vh.w, vl.w);
            *(uint4*)(smem + nbufo + a_soff) = vh;
            *(uint4*)(smem + nbufo + SM_AL_OFF + a_soff) = vl;
            CP_WAIT0();
        }
        __syncthreads();
    }

    int g = lane >> 2, t2 = (lane & 3) * 2;
    #pragma unroll
    for (int mt = 0; mt < 2; mt++) {
        int r0 = bm0 + mbase_w + mt * 16 + g;
        int r1 = r0 + 8;
        #pragma unroll
        for (int nt = 0; nt < 4; nt++) {
            int c = nb * 128 + nbase_w + nt * 8 + t2;
            float b0 = __ldg(&bias[c]), b1 = __ldg(&bias[c + 1]);
            if (r0 < M) *(__half2*)(C + (size_t)r0 * DD + c) =
                __floats2half2_rn(acc[mt][nt][0] + b0, acc[mt][nt][1] + b1);
            if (r1 < M) *(__half2*)(C + (size_t)r1 * DD + c) =
                __floats2half2_rn(acc[mt][nt][2] + b0, acc[mt][nt][3] + b1);
        }
    }
}

// ---- layer GEMM: packed split-bf16 A; rb_off = 64-row-block offset for row-split ----
template <bool HALF_OUT>
__global__ void __launch_bounds__(256, 3) hmma_gemm_pk(
    const unsigned char* __restrict__ Ah_g, const unsigned char* __restrict__ Al_g,
    const unsigned char* __restrict__ Bh_g, const unsigned char* __restrict__ Bl_g,
    const float* __restrict__ bias, void* __restrict__ Cv, int M, int rb_off)
{
    extern __shared__ __align__(16) unsigned char smem[];
    uint32_t sb = smem_to_u32(smem);
    int tid = threadIdx.x;
    int wid = tid >> 5, lane = tid & 31;
    int gbx = blockIdx.x + rb_off;
    int bm0 = gbx * 64;
    int nb = blockIdx.y;
    const int nIter = 8;
    size_t abase = (size_t)(gbx >> 1) * 8 * 10240 + (size_t)(gbx & 1) * 5120;

    int wr = wid >> 2, wc = wid & 3;
    int mbase_w = wr * 32;
    int nbase_w = wc * 32;

    int lj = lane >> 3, lr = lane & 7;
    uint32_t aoffA = (uint32_t)(((lj & 1) * 8 + lr) * AB_PITCH + (lj >> 1) * 16);
    uint32_t aoffB = (uint32_t)(((lj >> 1) * 8 + lr) * AB_PITCH + (lj & 1) * 16);

    float acc[2][4][4];
    #pragma unroll
    for (int mt = 0; mt < 2; mt++)
        #pragma unroll
        for (int nt = 0; nt < 4; nt++)
            #pragma unroll
            for (int i = 0; i < 4; i++) acc[mt][nt][i] = 0.f;

    {
        size_t tb = (size_t)nb * 10240;
        for (int c = tid; c < 320; c += 256) {
            cp16(sb + c * 16, Ah_g + abase + c * 16);
            cp16(sb + SM_AL_OFF + c * 16, Al_g + abase + c * 16);
        }
        for (int c = tid; c < 640; c += 256) {
            cp16(sb + SM_BH_OFF + c * 16, Bh_g + tb + c * 16);
            cp16(sb + SM_BL_OFF + c * 16, Bl_g + tb + c * 16);
        }
        CP_COMMIT();
        CP_WAIT0();
        __syncthreads();
    }

    for (int it = 0; it < nIter; it++) {
        uint32_t bufo = (uint32_t)((it & 1) * BUF_SZ);
        uint32_t nbufo = (uint32_t)(((it + 1) & 1) * BUF_SZ);
        bool more = (it + 1 < nIter);

        if (more) {
            size_t ta = abase + (size_t)(it + 1) * 10240;
            size_t tb = (size_t)(it + 1) * 20480 + (size_t)nb * 10240;
            for (int c = tid; c < 320; c += 256) {
                cp16(sb + nbufo + c * 16, Ah_g + ta + c * 16);
                cp16(sb + nbufo + SM_AL_OFF + c * 16, Al_g + ta + c * 16);
            }
            for (int c = tid; c < 640; c += 256) {
                cp16(sb + nbufo + SM_BH_OFF + c * 16, Bh_g + tb + c * 16);
                cp16(sb + nbufo + SM_BL_OFF + c * 16, Bl_g + tb + c * 16);
            }
            CP_COMMIT();
        }

        #pragma unroll
        for (int ks = 0; ks < 2; ks++) {
            uint32_t kof = (uint32_t)(ks * 32);
            uint32_t ah[2][4], al[2][4];
            #pragma unroll
            for (int mt = 0; mt < 2; mt++) {
                uint32_t base = sb + bufo + (uint32_t)((mbase_w + mt * 16) * AB_PITCH) + kof + aoffA;
                ldm4(ah[mt], base);
                ldm4(al[mt], base + SM_AL_OFF);
            }
            #pragma unroll
            for (int np = 0; np < 2; np++) {
                uint32_t bbase = sb + bufo + SM_BH_OFF + (uint32_t)((nbase_w + np * 16) * AB_PITCH) + kof + aoffB;
                uint32_t rh[4], rl[4];
                ldm4(rh, bbase);
                ldm4(rl, bbase + 10240);
                MMA_BLOCK(acc, ah, al, rh, rl, np);
            }
        }

        if (more) CP_WAIT0();
        __syncthreads();
    }

    int g = lane >> 2, t2 = (lane & 3) * 2;
    #pragma unroll
    for (int mt = 0; mt < 2; mt++) {
        int r0 = bm0 + mbase_w + mt * 16 + g;
        int r1 = r0 + 8;
        #pragma unroll
        for (int nt = 0; nt < 4; nt++) {
            int c = nb * 128 + nbase_w + nt * 8 + t2;
            float b0 = __ldg(&bias[c]), b1 = __ldg(&bias[c + 1]);
            if (HALF_OUT) {
                __half* C = (__half*)Cv;
                if (r0 < M) *(__half2*)(C + (size_t)r0 * DD + c) =
                    __floats2half2_rn(acc[mt][nt][0] + b0, acc[mt][nt][1] + b1);
                if (r1 < M) *(__half2*)(C + (size_t)r1 * DD + c) =
                    __floats2half2_rn(acc[mt][nt][2] + b0, acc[mt][nt][3] + b1);
            } else {
                float* C = (float*)Cv;
                if (r0 < M) *(float2*)(C + (size_t)r0 * DD + c) =
                    make_float2(acc[mt][nt][0] + b0, acc[mt][nt][1] + b1);
                if (r1 < M) *(float2*)(C + (size_t)r1 * DD + c) =
                    make_float2(acc[mt][nt][2] + b0, acc[mt][nt][3] + b1);
            }
        }
    }
}

// ---------------- BatchNorm + ELU (fp16 X) ----------------
__global__ void k_zero_bn() {
    int c = threadIdx.x;
    g_bns[c] = 0.f;
    g_bnq[c] = 0.f;
}
__global__ void k_bn_stats(const __half* __restrict__ X) {
    int c = threadIdx.x;
    int r0 = blockIdx.x * 256;
    int r1 = min(r0 + 256, NN);
    float s = 0.f, q = 0.f;
    for (int r = r0; r < r1; r++) {
        float v = __half2float(X[(size_t)r * DD + c]);
        s += v; q += v * v;
    }
    atomicAdd(&g_bns[c], s);
    atomicAdd(&g_bnq[c], q);
}
__global__ void k_bn_apply(__half* __restrict__ X,
                           const float* __restrict__ gamma,
                           const float* __restrict__ beta) {
    int idx = blockIdx.x * 256 + threadIdx.x;
    if (idx >= NN * (DD / 2)) return;
    int c2 = idx & 127;
    int c = c2 * 2;
    const float invN = 1.f / (float)NN;
    float2 sm = *(const float2*)&g_bns[c];
    float2 sq = *(const float2*)&g_bnq[c];
    float2 gm = *(const float2*)&gamma[c];
    float2 bt = *(const float2*)&beta[c];
    __half2 hx = ((__half2*)X)[idx];
    float2 x = __half22float2(hx);
    float mu, var, sc;
    float2 y;
    mu = sm.x * invN; var = sq.x * invN - mu * mu; sc = gm.x * rsqrtf(var + 1e-5f);
    y.x = sc * (x.x - mu) + bt.x;
    mu = sm.y * invN; var = sq.y * invN - mu * mu; sc = gm.y * rsqrtf(var + 1e-5f);
    y.y = sc * (x.y - mu) + bt.y;
    y.x = (y.x > 0.f) ? y.x : (__expf(y.x) - 1.f);
    y.y = (y.y > 0.f) ? y.y : (fexp_neg(y.y) - 1.f);
    ((__half2*)X)[idx] = __floats2half2_rn(y.x, y.y);
}

// ---------------- logits GEMM (reads fp32 out); blk_off for row-split ----------------
__global__ __launch_bounds__(320) void k_logits(
    const float* __restrict__ X, const float* __restrict__ W,
    const float* __restrict__ bias, float* __restrict__ O, int M, int blk_off)
{
    __shared__ float Xs[32][68];
    __shared__ float Ws[32][40];
    int tid = threadIdx.x;
    int bm0 = (blockIdx.x + blk_off) * 64;
    int rg = tid / 40;
    int col = tid % 40;
    float acc[8];
    #pragma unroll
    for (int i = 0; i < 8; i++) acc[i] = 0.f;

    for (int k0 = 0; k0 < DD; k0 += 32) {
        for (int idx = tid; idx < 512; idx += 320) {
            int row = idx >> 3;
            int kq = idx & 7;
            float4 v = make_float4(0.f, 0.f, 0.f, 0.f);
            int gr = bm0 + row;
            if (gr < M) v = *(const float4*)(X + (size_t)gr * DD + k0 + kq * 4);
            Xs[kq * 4 + 0][row] = v.x;
            Xs[kq * 4 + 1][row] = v.y;
            Xs[kq * 4 + 2][row] = v.z;
            Xs[kq * 4 + 3][row] = v.w;
        }
        for (int idx = tid; idx < 1280; idx += 320) {
            int k = idx / 40, c = idx % 40;
            Ws[k][c] = W[(size_t)(k0 + k) * CC + c];
        }
        __syncthreads();
        #pragma unroll
        for (int kk = 0; kk < 32; kk++) {
            float w = Ws[kk][col];
            float a0[4], a1[4];
            *(float4*)&a0[0] = *(float4*)&Xs[kk][rg * 8];
            *(float4*)&a1[0] = *(float4*)&Xs[kk][rg * 8 + 4];
            acc[0] += a0[0] * w; acc[1] += a0[1] * w;
            acc[2] += a0[2] * w; acc[3] += a0[3] * w;
            acc[4] += a1[0] * w; acc[5] += a1[1] * w;
            acc[6] += a1[2] * w; acc[7] += a1[3] * w;
        }
        __syncthreads();
    }
    float b = bias[col];
    #pragma unroll
    for (int i = 0; i < 8; i++) {
        int r = bm0 + rg * 8 + i;
        if (r < M) O[(size_t)r * CC + col] = acc[i] + b;
    }
}

// ---------------- static stream/event init ----------------
struct SideRes {
    cudaStream_t sB;
    cudaEvent_t evFork, evJoin;
    cudaEvent_t evA[3], evS[3], evL;
    SideRes() {
        cudaStreamCreateWithFlags(&sB, cudaStreamNonBlocking);
        cudaEventCreateWithFlags(&evFork, cudaEventDisableTiming);
        cudaEventCreateWithFlags(&evJoin, cudaEventDisableTiming);
        for (int i = 0; i < 3; i++) {
            cudaEventCreateWithFlags(&evA[i], cudaEventDisableTiming);
            cudaEventCreateWithFlags(&evS[i], cudaEventDisableTiming);
        }
        cudaEventCreateWithFlags(&evL, cudaEventDisableTiming);
        cudaFuncSetAttribute(hmma_gemm_fc, cudaFuncAttributeMaxDynamicSharedMemorySize, SMEM_GEMM);
        cudaFuncSetAttribute(hmma_gemm_pk<true>,  cudaFuncAttributeMaxDynamicSharedMemorySize, SMEM_GEMM);
        cudaFuncSetAttribute(hmma_gemm_pk<false>, cudaFuncAttributeMaxDynamicSharedMemorySize, SMEM_GEMM);
    }
};
static SideRes g_sr;

// ---------------- driver ----------------
extern "C" void kernel_launch(void* const* d_in, const int* in_sizes, int n_in,
                              void* d_out, int out_size)
{
    const float* feat  = (const float*)d_in[0];
    const int*   src   = (const int*)d_in[1];
    const int*   dst   = (const int*)d_in[2];
    const float* W_fc  = (const float*)d_in[3];
    const float* b_fc  = (const float*)d_in[4];
    const float* W1    = (const float*)d_in[5];
    const float* b1    = (const float*)d_in[6];
    const float* W2    = (const float*)d_in[7];
    const float* b2    = (const float*)d_in[8];
    const float* W3    = (const float*)d_in[9];
    const float* b3    = (const float*)d_in[10];
    const float* gamma = (const float*)d_in[11];
    const float* beta  = (const float*)d_in[12];
    const float* W_lin = (const float*)d_in[13];
    const float* b_lin = (const float*)d_in[14];
    float* out = (float*)d_out;

    __half *gXa, *gXb;
    cudaGetSymbolAddress((void**)&gXa, g_Xa);
    cudaGetSymbolAddress((void**)&gXb, g_Xb);
    unsigned char *gAh, *gAl;
    cudaGetSymbolAddress((void**)&gAh, g_Ah);
    cudaGetSymbolAddress((void**)&gAl, g_Al);
    unsigned char *pFh, *pFl, *p1h, *p1l, *p2h, *p2l, *p3h, *p3l;
    cudaGetSymbolAddress((void**)&pFh, g_Wfc_h);
    cudaGetSymbolAddress((void**)&pFl, g_Wfc_l);
    cudaGetSymbolAddress((void**)&p1h, g_W1_h);
    cudaGetSymbolAddress((void**)&p1l, g_W1_l);
    cudaGetSymbolAddress((void**)&p2h, g_W2_h);
    cudaGetSymbolAddress((void**)&p2l, g_W2_l);
    cudaGetSymbolAddress((void**)&p3h, g_W3_h);
    cudaGetSymbolAddress((void**)&p3l, g_W3_l);

    const int NB_N = (NN + 255) / 256;
    const int NB_E = (EE + 255) / 256;
    dim3 gemm_grid((NN + 63) / 64, 2);          // fc full grid
    dim3 pk_half(RB_HALF, 2);                   // 391 x 2 per half
    dim3 spmm_block(32, 8);
    const int SPMM_H0 = H0_NODES / 8;           // 3128
    const int SPMM_H1 = (NN - H0_NODES + 7) / 8; // 3122
    int bn_grid = (NN * (DD / 2) + 255) / 256;
    cudaStream_t sB = g_sr.sB;

    // ---- fork: side = graph prep + layer prepacks + bn zero ----
    cudaEventRecord(g_sr.evFork, 0);
    cudaStreamWaitEvent(sB, g_sr.evFork, 0);

    k_zero_prep<<<NB_N, 256, 0, sB>>>();
    k_count<<<NB_E, 256, 0, sB>>>(src, dst);
    k_prepack<<<(DD * (FF / 8) + 255) / 256, 256>>>(W_fc, pFh, pFl, FF);              // main
    hmma_gemm_fc<<<gemm_grid, 256, SMEM_GEMM>>>(feat, pFh, pFl, b_fc, gXa, NN, FF);   // main
    k_norms<<<NB_N, 256, 0, sB>>>();
    k_scan1<<<49, 1024, 0, sB>>>();
    k_scan2<<<1, 64, 0, sB>>>();
    k_scan3<<<NB_N, 256, 0, sB>>>();
    k_fill<<<NB_E, 256, 0, sB>>>(src, dst);
    k_prepack<<<(DD * (DD / 8) + 255) / 256, 256, 0, sB>>>(W1, p1h, p1l, DD);
    k_prepack<<<(DD * (DD / 8) + 255) / 256, 256, 0, sB>>>(W2, p2h, p2l, DD);
    k_prepack<<<(DD * (DD / 8) + 255) / 256, 256, 0, sB>>>(W3, p3h, p3l, DD);
    k_zero_bn<<<1, 256, 0, sB>>>();
    cudaEventRecord(g_sr.evJoin, sB);

    // fc done -> side may start layer-1 half1 (side already ordered after prep)
    cudaEventRecord(g_sr.evA[0], 0);
    cudaStreamWaitEvent(sB, g_sr.evA[0], 0);
    // main needs prep (rowptr) before spmm h0
    cudaStreamWaitEvent(0, g_sr.evJoin, 0);

    // ---- layer 1: Xa -> Xb ----
    k_spmm<<<SPMM_H1, spmm_block, 0, sB>>>(gXa, H0_NODES);
    hmma_gemm_pk<true><<<pk_half, 256, SMEM_GEMM, sB>>>(gAh, gAl, p1h, p1l, b1, gXb, NN, RB_HALF);
    cudaEventRecord(g_sr.evS[0], sB);
    k_spmm<<<SPMM_H0, spmm_block>>>(gXa, 0);
    hmma_gemm_pk<true><<<pk_half, 256, SMEM_GEMM>>>(gAh, gAl, p1h, p1l, b1, gXb, NN, 0);
    cudaStreamWaitEvent(0, g_sr.evS[0], 0);
    k_bn_stats<<<NB_N, 256>>>(gXb);
    k_bn_apply<<<bn_grid, 256>>>(gXb, gamma, beta);
    k_zero_bn<<<1, 256>>>();

    // ---- layer 2: Xb -> Xa ----
    cudaEventRecord(g_sr.evA[1], 0);
    cudaStreamWaitEvent(sB, g_sr.evA[1], 0);
    k_spmm<<<SPMM_H1, spmm_block, 0, sB>>>(gXb, H0_NODES);
    hmma_gemm_pk<true><<<pk_half, 256, SMEM_GEMM, sB>>>(gAh, gAl, p2h, p2l, b2, gXa, NN, RB_HALF);
    cudaEventRecord(g_sr.evS[1], sB);
    k_spmm<<<SPMM_H0, spmm_block>>>(gXb, 0);
    hmma_gemm_pk<true><<<pk_half, 256, SMEM_GEMM>>>(gAh, gAl, p2h, p2l, b2, gXa, NN, 0);
    cudaStreamWaitEvent(0, g_sr.evS[1], 0);
    k_bn_stats<<<NB_N, 256>>>(gXa);
    k_bn_apply<<<bn_grid, 256>>>(gXa, gamma, beta);

    // ---- layer 3: Xa -> out (fp32), + logits, both row-split ----
    cudaEventRecord(g_sr.evA[2], 0);
    cudaStreamWaitEvent(sB, g_sr.evA[2], 0);
    k_spmm<<<SPMM_H1, spmm_block, 0, sB>>>(gXa, H0_NODES);
    hmma_gemm_pk<false><<<pk_half, 256, SMEM_GEMM, sB>>>(gAh, gAl, p3h, p3l, b3, out, NN, RB_HALF);
    k_logits<<<RB_HALF, 320, 0, sB>>>(out, W_lin, b_lin, out + (size_t)NN * DD, NN, RB_HALF);
    cudaEventRecord(g_sr.evL, sB);
    k_spmm<<<SPMM_H0, spmm_block>>>(gXa, 0);
    hmma_gemm_pk<false><<<pk_half, 256, SMEM_GEMM>>>(gAh, gAl, p3h, p3l, b3, out, NN, 0);
    k_logits<<<RB_HALF, 320>>>(out, W_lin, b_lin, out + (size_t)NN * DD, NN, 0);
    cudaStreamWaitEvent(0, g_sr.evL, 0);
}